// round 9
// baseline (speedup 1.0000x reference)
#include <cuda_runtime.h>
#include <math_constants.h>
#include <mma.h>
#include <cuda_fp16.h>
#include <cstdint>

using namespace nvcuda;

#define BATCH 8
#define NPTS  4096
#define KNN   20
#define CIN   26
#define C1    64
#define C2    64
#define C3    128
#define C4    256
#define CCAT  512
#define EMB   512

__device__ int   g_idx[BATCH * NPTS * KNN];
__device__ float g_cat[(size_t)BATCH * NPTS * CCAT];     // 64 MB

// ===================== Kernel 1: exact 20-NN =====================
// 2 threads/point (consecutive lanes), 4-wide scan, shared-threshold pruning,
// lexicographic merge (exactly reproduces jax.lax.top_k ordering).
__global__ __launch_bounds__(128) void knn_kernel(const float* __restrict__ x) {
    extern __shared__ float4 xs[];          // 4096*16 = 64KB
    __shared__ float mv[64][KNN];
    __shared__ int   mi[64][KNN];
    const int b = blockIdx.y;
    const float* xb = x + (size_t)b * 3 * NPTS;
    for (int m = threadIdx.x; m < NPTS; m += 128) {
        float x0 = xb[m], x1 = xb[NPTS + m], x2 = xb[2 * NPTS + m];
        xs[m] = make_float4(x0, x1, x2, fmaf(x0, x0, fmaf(x1, x1, x2 * x2)));
    }
    __syncthreads();
    const int lp = threadIdx.x >> 1;        // local point 0..63
    const int c  = threadIdx.x & 1;         // half 0..1 (lanes 2k, 2k+1 pair)
    const int n  = blockIdx.x * 64 + lp;
    float4 p = xs[n];
    const float a0 = -2.f * p.x, a1 = -2.f * p.y, a2 = -2.f * p.z;
    float bv[KNN]; int bi[KNN];
#pragma unroll
    for (int t = 0; t < KNN; ++t) { bv[t] = CUDART_INF_F; bi[t] = 0x7FFFFFFF; }
    float th_other = CUDART_INF_F;

    const int m0 = c * 2048;
#pragma unroll 2
    for (int mm = 0; mm < 2048; mm += 4) {
        const int m = m0 + mm;
        float4 q0 = xs[m], q1 = xs[m + 1], q2 = xs[m + 2], q3 = xs[m + 3];
        float v0 = fmaf(a0, q0.x, fmaf(a1, q0.y, fmaf(a2, q0.z, q0.w)));
        float v1 = fmaf(a0, q1.x, fmaf(a1, q1.y, fmaf(a2, q1.z, q1.w)));
        float v2 = fmaf(a0, q2.x, fmaf(a1, q2.y, fmaf(a2, q2.z, q2.w)));
        float v3 = fmaf(a0, q3.x, fmaf(a1, q3.y, fmaf(a2, q3.z, q3.w)));
        float vm = fminf(fminf(v0, v1), fminf(v2, v3));
        if (vm < bv[KNN - 1] && vm <= th_other) {
#pragma unroll
            for (int j = 0; j < 4; ++j) {
                float v = (j == 0) ? v0 : (j == 1) ? v1 : (j == 2) ? v2 : v3;
                if (v < bv[KNN - 1] && v <= th_other) {
                    bool ins = true;
#pragma unroll
                    for (int t = KNN - 1; t >= 1; --t) {
                        bool sh = v < bv[t - 1];
                        if (sh)       { bv[t] = bv[t - 1]; bi[t] = bi[t - 1]; }
                        else if (ins) { bv[t] = v;         bi[t] = m + j; }
                        ins = sh;
                    }
                    if (ins) { bv[0] = v; bi[0] = m + j; }
                }
            }
        }
        if ((mm & 255) == 252)   // uniform across warp: safe shfl
            th_other = __shfl_xor_sync(0xffffffffu, bv[KNN - 1], 1);
    }

    if (c == 1) {
#pragma unroll
        for (int t = 0; t < KNN; ++t) { mv[lp][t] = bv[t]; mi[lp][t] = bi[t]; }
    }
    __syncthreads();
    if (c == 0) {
#pragma unroll
        for (int e = 0; e < KNN; ++e) {
            float v = mv[lp][e]; int i = mi[lp][e];
            if (v < bv[KNN - 1] || (v == bv[KNN - 1] && i < bi[KNN - 1])) {
                bool ins = true;
#pragma unroll
                for (int t = KNN - 1; t >= 1; --t) {
                    bool sh = (v < bv[t - 1]) || (v == bv[t - 1] && i < bi[t - 1]);
                    if (sh)       { bv[t] = bv[t - 1]; bi[t] = bi[t - 1]; }
                    else if (ins) { bv[t] = v;         bi[t] = i; }
                    ins = sh;
                }
                if (ins) { bv[0] = v; bi[0] = i; }
            } else break;   // sorted input: first miss ends merge
        }
        int* outp = g_idx + ((size_t)b * NPTS + n) * KNN;
#pragma unroll
        for (int t = 0; t < KNN; ++t) outp[t] = bi[t];
    }
}

// ===================== Kernel 2: fused L1(scalar) + L2/L3/L4 (wmma fp16) =====================
#define LPTS 8
#define LROWS (LPTS * KNN)   // 160
#define HBLD 136             // halves
#define H2LD2 72             // halves

typedef wmma::fragment<wmma::matrix_a, 16, 16, 16, half, wmma::row_major> HA;
typedef wmma::fragment<wmma::matrix_b, 16, 16, 16, half, wmma::col_major> HB;
typedef wmma::fragment<wmma::accumulator, 16, 16, 16, float> HCf;
typedef wmma::fragment<wmma::accumulator, 16, 16, 16, half>  HCh;

__device__ __forceinline__ void store_relu_half(half* dst, int ld, HCf& cf) {
    HCh ch;
#pragma unroll
    for (int i = 0; i < cf.num_elements; ++i)
        ch.x[i] = __float2half_rn(fmaxf(cf.x[i], 0.f));
    wmma::store_matrix_sync(dst, ch, ld, wmma::mem_row_major);
}

__global__ __launch_bounds__(256, 2) void l1234_kernel(
    const float* __restrict__ x,
    const float* __restrict__ w1, const float* __restrict__ w2,
    const float* __restrict__ w3, const float* __restrict__ w4) {
    extern __shared__ half hsm[];
    half* hb   = hsm;                        // 160*136 (h1, then h3)
    half* h2b  = hb + LROWS * HBLD;          // 160*72 (h2 / h4-chunk)
    half* wbuf = h2b + LROWS * H2LD2;        // 9216 h (W2/W3/W4-chunk)
    __shared__ float W1t[CIN * C1];
    __shared__ float s_nbr[LPTS][KNN][3];
    __shared__ float s_dist[LPTS][KNN];
    __shared__ float s_xn[LPTS][3];

    const int tid = threadIdx.x, warp = tid >> 5;
    const size_t pt0 = (size_t)blockIdx.x * LPTS;

    for (int i = tid; i < CIN * C1; i += 256) { int o = i / CIN, c = i % CIN; W1t[c * C1 + o] = w1[i]; }
    for (int i = tid; i < C2 * C2;  i += 256) { int o = i >> 6, c = i & 63; wbuf[o * H2LD2 + c] = __float2half_rn(w2[i]); }

    if (tid < LPTS * KNN) {
        int p = tid / KNN, k = tid % KNN;
        size_t pt = pt0 + p;
        int b = (int)(pt >> 12), n = (int)(pt & (NPTS - 1));
        const float* xb = x + (size_t)b * 3 * NPTS;
        int nb = g_idx[pt * KNN + k];
        float c0 = xb[n], c1 = xb[NPTS + n], c2 = xb[2 * NPTS + n];
        float n0 = xb[nb], n1 = xb[NPTS + nb], n2 = xb[2 * NPTS + nb];
        s_nbr[p][k][0] = n0; s_nbr[p][k][1] = n1; s_nbr[p][k][2] = n2;
        float d0 = n0 - c0, d1 = n1 - c1, d2 = n2 - c2;
        s_dist[p][k] = sqrtf(fmaf(d0, d0, fmaf(d1, d1, d2 * d2)) + 1e-12f);
        if (k < 3) s_xn[p][k] = xb[k * NPTS + n];
    }
    __syncthreads();

    // L1 scalar -> hb (half), x1 -> cat[0:64]
    {
        int o = tid & 63;
#pragma unroll
        for (int pi = 0; pi < 2; ++pi) {
            int p = (tid >> 6) + pi * 4;
            float base = 0.f;
#pragma unroll
            for (int d = 0; d < 3; ++d) base = fmaf(W1t[d * C1 + o], s_xn[p][d], base);
#pragma unroll
            for (int j = 0; j < KNN; ++j) base = fmaf(W1t[(6 + j) * C1 + o], s_dist[p][j], base);
            float wa = W1t[3 * C1 + o], wb = W1t[4 * C1 + o], wc = W1t[5 * C1 + o];
            float mx = 0.f;
#pragma unroll
            for (int k = 0; k < KNN; ++k) {
                float v = fmaf(wa, s_nbr[p][k][0], fmaf(wb, s_nbr[p][k][1], fmaf(wc, s_nbr[p][k][2], base)));
                v = fmaxf(v, 0.f);
                mx = fmaxf(mx, v);
                hb[(p * KNN + k) * HBLD + o] = __float2half_rn(v);
            }
            g_cat[(pt0 + p) * CCAT + o] = mx;
        }
    }
    __syncthreads();

    // L2: M=160,N=64,K=64 -> h2b
    {
        HA fa; HB fb; HCf fc;
        for (int t = warp; t < 40; t += 8) {
            int mt = t >> 2, nt = t & 3;
            wmma::fill_fragment(fc, 0.f);
#pragma unroll
            for (int kt = 0; kt < 4; ++kt) {
                wmma::load_matrix_sync(fa, hb + mt * 16 * HBLD + kt * 16, HBLD);
                wmma::load_matrix_sync(fb, wbuf + nt * 16 * H2LD2 + kt * 16, H2LD2);
                wmma::mma_sync(fc, fa, fb, fc);
            }
            store_relu_half(h2b + mt * 16 * H2LD2 + nt * 16, H2LD2, fc);
        }
    }
    __syncthreads();

    // x2 -> cat[64:128]
    {
        int o = tid & 63;
#pragma unroll
        for (int pi = 0; pi < 2; ++pi) {
            int p = (tid >> 6) + pi * 4;
            float mx = 0.f;
#pragma unroll
            for (int k = 0; k < KNN; ++k)
                mx = fmaxf(mx, __half2float(h2b[(p * KNN + k) * H2LD2 + o]));
            g_cat[(pt0 + p) * CCAT + 64 + o] = mx;
        }
    }
    __syncthreads();

    for (int i = tid; i < C3 * C2; i += 256) { int o = i >> 6, c = i & 63; wbuf[o * H2LD2 + c] = __float2half_rn(w3[i]); }
    __syncthreads();

    // L3: M=160,N=128,K=64 -> hb
    {
        HA fa; HB fb; HCf fc;
        for (int t = warp; t < 80; t += 8) {
            int mt = t >> 3, nt = t & 7;
            wmma::fill_fragment(fc, 0.f);
#pragma unroll
            for (int kt = 0; kt < 4; ++kt) {
                wmma::load_matrix_sync(fa, h2b + mt * 16 * H2LD2 + kt * 16, H2LD2);
                wmma::load_matrix_sync(fb, wbuf + nt * 16 * H2LD2 + kt * 16, H2LD2);
                wmma::mma_sync(fc, fa, fb, fc);
            }
            store_relu_half(hb + mt * 16 * HBLD + nt * 16, HBLD, fc);
        }
    }
    __syncthreads();

    // x3 -> cat[128:256]
    {
        int oc = tid & 127;
#pragma unroll
        for (int pi = 0; pi < 4; ++pi) {
            int p = (tid >> 7) + pi * 2;
            float mx = 0.f;
#pragma unroll
            for (int r = 0; r < KNN; ++r)
                mx = fmaxf(mx, __half2float(hb[(p * KNN + r) * HBLD + oc]));
            g_cat[(pt0 + p) * CCAT + 128 + oc] = mx;
        }
    }
    __syncthreads();

    // L4: M=160,N=256(4x64),K=128
    for (int co = 0; co < 4; ++co) {
        for (int i = tid; i < 64 * 128; i += 256) {
            int o = i >> 7, k = i & 127;
            wbuf[o * HBLD + k] = __float2half_rn(w4[(size_t)(co * 64 + o) * 128 + k]);
        }
        __syncthreads();
        {
            HA fa; HB fb; HCf fc;
            for (int t = warp; t < 40; t += 8) {
                int mt = t >> 2, nt = t & 3;
                wmma::fill_fragment(fc, 0.f);
#pragma unroll
                for (int kt = 0; kt < 8; ++kt) {
                    wmma::load_matrix_sync(fa, hb + mt * 16 * HBLD + kt * 16, HBLD);
                    wmma::load_matrix_sync(fb, wbuf + nt * 16 * HBLD + kt * 16, HBLD);
                    wmma::mma_sync(fc, fa, fb, fc);
                }
                store_relu_half(h2b + mt * 16 * H2LD2 + nt * 16, H2LD2, fc);
            }
        }
        __syncthreads();
        {
            int o = tid & 63;
#pragma unroll
            for (int pi = 0; pi < 2; ++pi) {
                int p = (tid >> 6) + pi * 4;
                float mx = 0.f;
#pragma unroll
                for (int r = 0; r < KNN; ++r)
                    mx = fmaxf(mx, __half2float(h2b[(p * KNN + r) * H2LD2 + o]));
                g_cat[(pt0 + p) * CCAT + 256 + co * 64 + o] = mx;
            }
        }
        __syncthreads();
    }
}

// ===================== Kernel 3: L5 tiled GEMM (wmma fp16) =====================
#define KC5   64
#define ALD5  72
#define TILEH (128 * ALD5)

__global__ __launch_bounds__(256, 2) void l5_kernel(
    const float* __restrict__ w5, float* __restrict__ out) {
    extern __shared__ half hsm[];
    half* bufA[2] = { hsm,         hsm + 2 * TILEH };
    half* bufB[2] = { hsm + TILEH, hsm + 3 * TILEH };

    const int tid = threadIdx.x, warp = tid >> 5;
    const int n0 = blockIdx.x * 128;
    const int o0 = blockIdx.y * 128;
    const int b  = blockIdx.z;
    const float* catg = g_cat + ((size_t)b * NPTS + n0) * CCAT;
    const float* wg   = w5 + (size_t)o0 * CCAT;
    const int wr = warp >> 2, wc = warp & 3;

    HCf fc[4][2];
#pragma unroll
    for (int i = 0; i < 4; ++i) { wmma::fill_fragment(fc[i][0], 0.f); wmma::fill_fragment(fc[i][1], 0.f); }

    auto stage = [&](int kc, int bi) {
        half* pa = bufA[bi]; half* pb = bufB[bi];
#pragma unroll
        for (int it = 0; it < 8; ++it) {
            int lin = tid + it * 256;
            int r = lin >> 4, q = lin & 15;
            float4 a = *(const float4*)(wg   + (size_t)r * CCAT + kc * KC5 + q * 4);
            float4 c = *(const float4*)(catg + (size_t)r * CCAT + kc * KC5 + q * 4);
            *(half2*)(pa + r * ALD5 + q * 4)     = __floats2half2_rn(a.x, a.y);
            *(half2*)(pa + r * ALD5 + q * 4 + 2) = __floats2half2_rn(a.z, a.w);
            *(half2*)(pb + r * ALD5 + q * 4)     = __floats2half2_rn(c.x, c.y);
            *(half2*)(pb + r * ALD5 + q * 4 + 2) = __floats2half2_rn(c.z, c.w);
        }
    };

    stage(0, 0);
    __syncthreads();

    HA fa; HB fb;
    for (int kc = 0; kc < 8; ++kc) {
        const int cur = kc & 1;
        if (kc + 1 < 8) stage(kc + 1, cur ^ 1);
        const half* A = bufA[cur];
        const half* B = bufB[cur];
#pragma unroll
        for (int kt = 0; kt < 4; ++kt) {
#pragma unroll
            for (int j = 0; j < 2; ++j) {
                wmma::load_matrix_sync(fb, B + (wc * 32 + j * 16) * ALD5 + kt * 16, ALD5);
#pragma unroll
                for (int i = 0; i < 4; ++i) {
                    wmma::load_matrix_sync(fa, A + (wr * 64 + i * 16) * ALD5 + kt * 16, ALD5);
                    wmma::mma_sync(fc[i][j], fa, fb, fc[i][j]);
                }
            }
        }
        __syncthreads();
    }

    float* scratch = (float*)hsm;
#pragma unroll
    for (int i = 0; i < 4; ++i)
#pragma unroll
        for (int j = 0; j < 2; ++j)
            wmma::store_matrix_sync(scratch + (wr * 64 + i * 16) * 132 + wc * 32 + j * 16,
                                    fc[i][j], 132, wmma::mem_row_major);
    __syncthreads();

    for (int i = tid; i < 128 * 128; i += 256) {
        int o = i >> 7, n = i & 127;
        out[((size_t)b * EMB + o0 + o) * NPTS + n0 + n] = fmaxf(scratch[o * 132 + n], 0.f);
    }
}

// ===================== launch =====================
extern "C" void kernel_launch(void* const* d_in, const int* in_sizes, int n_in,
                              void* d_out, int out_size) {
    const float* x  = (const float*)d_in[0];
    const float* w1 = (const float*)d_in[1];
    const float* w2 = (const float*)d_in[2];
    const float* w3 = (const float*)d_in[3];
    const float* w4 = (const float*)d_in[4];
    const float* w5 = (const float*)d_in[5];
    float* out = (float*)d_out;

    const int knn_smem   = NPTS * sizeof(float4);                                       // 64 KB dyn
    const int l1234_smem = (LROWS * HBLD + LROWS * H2LD2 + 128 * H2LD2) * sizeof(half); // ~85 KB
    const int l5_smem    = 4 * TILEH * sizeof(half);                                    // 72 KB
    cudaFuncSetAttribute(knn_kernel,   cudaFuncAttributeMaxDynamicSharedMemorySize, knn_smem);
    cudaFuncSetAttribute(l1234_kernel, cudaFuncAttributeMaxDynamicSharedMemorySize, l1234_smem);
    cudaFuncSetAttribute(l5_kernel,    cudaFuncAttributeMaxDynamicSharedMemorySize, l5_smem);

    knn_kernel<<<dim3(NPTS / 64, BATCH), 128, knn_smem>>>(x);
    l1234_kernel<<<(BATCH * NPTS) / LPTS, 256, l1234_smem>>>(x, w1, w2, w3, w4);
    l5_kernel<<<dim3(NPTS / 128, EMB / 128, BATCH), 256, l5_smem>>>(w5, out);
}

// round 10
// speedup vs baseline: 1.1476x; 1.1476x over previous
#include <cuda_runtime.h>
#include <math_constants.h>
#include <mma.h>
#include <cuda_fp16.h>
#include <cstdint>

using namespace nvcuda;

#define BATCH 8
#define NPTS  4096
#define KNN   20
#define CIN   26
#define C1    64
#define C2    64
#define C3    128
#define C4    256
#define CCAT  512
#define EMB   512

__device__ int    g_idx[BATCH * NPTS * KNN];
__device__ __half g_cat[(size_t)BATCH * NPTS * CCAT];   // 32 MB (half)
__device__ __half g_w5h[EMB * CCAT];                    // 0.5 MB

// ===================== Kernel 0: w5 -> half =====================
__global__ __launch_bounds__(256) void wconv_kernel(const float* __restrict__ w5) {
    int i = (blockIdx.x * 256 + threadIdx.x) * 4;
    float4 v = *(const float4*)(w5 + i);
    *(half2*)(g_w5h + i)     = __floats2half2_rn(v.x, v.y);
    *(half2*)(g_w5h + i + 2) = __floats2half2_rn(v.z, v.w);
}

// ===================== Kernel 1: exact 20-NN (1 thread/point, best measured) =====================
__global__ __launch_bounds__(128) void knn_kernel(const float* __restrict__ x) {
    extern __shared__ float4 xs[];   // 64KB
    const int b = blockIdx.y;
    const float* xb = x + (size_t)b * 3 * NPTS;
    for (int m = threadIdx.x; m < NPTS; m += blockDim.x) {
        float x0 = xb[m], x1 = xb[NPTS + m], x2 = xb[2 * NPTS + m];
        xs[m] = make_float4(x0, x1, x2, fmaf(x0, x0, fmaf(x1, x1, x2 * x2)));
    }
    __syncthreads();
    const int n = blockIdx.x * blockDim.x + threadIdx.x;
    float4 p = xs[n];
    const float a0 = -2.f * p.x, a1 = -2.f * p.y, a2 = -2.f * p.z;
    float bv[KNN]; int bi[KNN];
#pragma unroll
    for (int t = 0; t < KNN; ++t) { bv[t] = CUDART_INF_F; bi[t] = -1; }
#pragma unroll 4
    for (int m = 0; m < NPTS; ++m) {
        float4 q = xs[m];
        float v = fmaf(a0, q.x, fmaf(a1, q.y, fmaf(a2, q.z, q.w)));
        if (v < bv[KNN - 1]) {
            bool ins = true;
#pragma unroll
            for (int t = KNN - 1; t >= 1; --t) {
                bool sh = v < bv[t - 1];
                if (sh)       { bv[t] = bv[t - 1]; bi[t] = bi[t - 1]; }
                else if (ins) { bv[t] = v;         bi[t] = m; }
                ins = sh;
            }
            if (ins) { bv[0] = v; bi[0] = m; }
        }
    }
    int* outp = g_idx + ((size_t)b * NPTS + n) * KNN;
#pragma unroll
    for (int t = 0; t < KNN; ++t) outp[t] = bi[t];
}

// ===================== Kernel 2: fused L1(scalar) + L2/L3/L4 (wmma fp16) =====================
#define LPTS 8
#define LROWS (LPTS * KNN)   // 160
#define HBLD 136             // halves
#define H2LD2 72             // halves

typedef wmma::fragment<wmma::matrix_a, 16, 16, 16, half, wmma::row_major> HA;
typedef wmma::fragment<wmma::matrix_b, 16, 16, 16, half, wmma::col_major> HB;
typedef wmma::fragment<wmma::accumulator, 16, 16, 16, float> HCf;
typedef wmma::fragment<wmma::accumulator, 16, 16, 16, half>  HCh;

__device__ __forceinline__ void store_relu_half(half* dst, int ld, HCf& cf) {
    HCh ch;
#pragma unroll
    for (int i = 0; i < cf.num_elements; ++i)
        ch.x[i] = __float2half_rn(fmaxf(cf.x[i], 0.f));
    wmma::store_matrix_sync(dst, ch, ld, wmma::mem_row_major);
}

__global__ __launch_bounds__(256, 2) void l1234_kernel(
    const float* __restrict__ x,
    const float* __restrict__ w1, const float* __restrict__ w2,
    const float* __restrict__ w3, const float* __restrict__ w4) {
    extern __shared__ half hsm[];
    half* hb   = hsm;                        // 160*136 (h1, then h3)
    half* h2b  = hb + LROWS * HBLD;          // 160*72 (h2 / h4-chunk)
    half* wbuf = h2b + LROWS * H2LD2;        // 9216 h (W2/W3/W4-chunk)
    __shared__ float W1t[CIN * C1];
    __shared__ float s_nbr[LPTS][KNN][3];
    __shared__ float s_dist[LPTS][KNN];
    __shared__ float s_xn[LPTS][3];

    const int tid = threadIdx.x, warp = tid >> 5;
    const size_t pt0 = (size_t)blockIdx.x * LPTS;

    for (int i = tid; i < CIN * C1; i += 256) { int o = i / CIN, c = i % CIN; W1t[c * C1 + o] = w1[i]; }
    for (int i = tid; i < C2 * C2;  i += 256) { int o = i >> 6, c = i & 63; wbuf[o * H2LD2 + c] = __float2half_rn(w2[i]); }

    if (tid < LPTS * KNN) {
        int p = tid / KNN, k = tid % KNN;
        size_t pt = pt0 + p;
        int b = (int)(pt >> 12), n = (int)(pt & (NPTS - 1));
        const float* xb = x + (size_t)b * 3 * NPTS;
        int nb = g_idx[pt * KNN + k];
        float c0 = xb[n], c1 = xb[NPTS + n], c2 = xb[2 * NPTS + n];
        float n0 = xb[nb], n1 = xb[NPTS + nb], n2 = xb[2 * NPTS + nb];
        s_nbr[p][k][0] = n0; s_nbr[p][k][1] = n1; s_nbr[p][k][2] = n2;
        float d0 = n0 - c0, d1 = n1 - c1, d2 = n2 - c2;
        s_dist[p][k] = sqrtf(fmaf(d0, d0, fmaf(d1, d1, d2 * d2)) + 1e-12f);
        if (k < 3) s_xn[p][k] = xb[k * NPTS + n];
    }
    __syncthreads();

    // L1 scalar -> hb (half), x1 -> cat[0:64]
    {
        int o = tid & 63;
#pragma unroll
        for (int pi = 0; pi < 2; ++pi) {
            int p = (tid >> 6) + pi * 4;
            float base = 0.f;
#pragma unroll
            for (int d = 0; d < 3; ++d) base = fmaf(W1t[d * C1 + o], s_xn[p][d], base);
#pragma unroll
            for (int j = 0; j < KNN; ++j) base = fmaf(W1t[(6 + j) * C1 + o], s_dist[p][j], base);
            float wa = W1t[3 * C1 + o], wb = W1t[4 * C1 + o], wc = W1t[5 * C1 + o];
            float mx = 0.f;
#pragma unroll
            for (int k = 0; k < KNN; ++k) {
                float v = fmaf(wa, s_nbr[p][k][0], fmaf(wb, s_nbr[p][k][1], fmaf(wc, s_nbr[p][k][2], base)));
                v = fmaxf(v, 0.f);
                mx = fmaxf(mx, v);
                hb[(p * KNN + k) * HBLD + o] = __float2half_rn(v);
            }
            g_cat[(pt0 + p) * CCAT + o] = __float2half_rn(mx);
        }
    }
    __syncthreads();

    // L2: M=160,N=64,K=64 -> h2b
    {
        HA fa; HB fb; HCf fc;
        for (int t = warp; t < 40; t += 8) {
            int mt = t >> 2, nt = t & 3;
            wmma::fill_fragment(fc, 0.f);
#pragma unroll
            for (int kt = 0; kt < 4; ++kt) {
                wmma::load_matrix_sync(fa, hb + mt * 16 * HBLD + kt * 16, HBLD);
                wmma::load_matrix_sync(fb, wbuf + nt * 16 * H2LD2 + kt * 16, H2LD2);
                wmma::mma_sync(fc, fa, fb, fc);
            }
            store_relu_half(h2b + mt * 16 * H2LD2 + nt * 16, H2LD2, fc);
        }
    }
    __syncthreads();

    // x2 -> cat[64:128]
    {
        int o = tid & 63;
#pragma unroll
        for (int pi = 0; pi < 2; ++pi) {
            int p = (tid >> 6) + pi * 4;
            float mx = 0.f;
#pragma unroll
            for (int k = 0; k < KNN; ++k)
                mx = fmaxf(mx, __half2float(h2b[(p * KNN + k) * H2LD2 + o]));
            g_cat[(pt0 + p) * CCAT + 64 + o] = __float2half_rn(mx);
        }
    }
    __syncthreads();

    for (int i = tid; i < C3 * C2; i += 256) { int o = i >> 6, c = i & 63; wbuf[o * H2LD2 + c] = __float2half_rn(w3[i]); }
    __syncthreads();

    // L3: M=160,N=128,K=64 -> hb
    {
        HA fa; HB fb; HCf fc;
        for (int t = warp; t < 80; t += 8) {
            int mt = t >> 3, nt = t & 7;
            wmma::fill_fragment(fc, 0.f);
#pragma unroll
            for (int kt = 0; kt < 4; ++kt) {
                wmma::load_matrix_sync(fa, h2b + mt * 16 * H2LD2 + kt * 16, H2LD2);
                wmma::load_matrix_sync(fb, wbuf + nt * 16 * H2LD2 + kt * 16, H2LD2);
                wmma::mma_sync(fc, fa, fb, fc);
            }
            store_relu_half(hb + mt * 16 * HBLD + nt * 16, HBLD, fc);
        }
    }
    __syncthreads();

    // x3 -> cat[128:256]
    {
        int oc = tid & 127;
#pragma unroll
        for (int pi = 0; pi < 4; ++pi) {
            int p = (tid >> 7) + pi * 2;
            float mx = 0.f;
#pragma unroll
            for (int r = 0; r < KNN; ++r)
                mx = fmaxf(mx, __half2float(hb[(p * KNN + r) * HBLD + oc]));
            g_cat[(pt0 + p) * CCAT + 128 + oc] = __float2half_rn(mx);
        }
    }
    __syncthreads();

    // L4: M=160,N=256(4x64),K=128
    for (int co = 0; co < 4; ++co) {
        for (int i = tid; i < 64 * 128; i += 256) {
            int o = i >> 7, k = i & 127;
            wbuf[o * HBLD + k] = __float2half_rn(w4[(size_t)(co * 64 + o) * 128 + k]);
        }
        __syncthreads();
        {
            HA fa; HB fb; HCf fc;
            for (int t = warp; t < 40; t += 8) {
                int mt = t >> 2, nt = t & 3;
                wmma::fill_fragment(fc, 0.f);
#pragma unroll
                for (int kt = 0; kt < 8; ++kt) {
                    wmma::load_matrix_sync(fa, hb + mt * 16 * HBLD + kt * 16, HBLD);
                    wmma::load_matrix_sync(fb, wbuf + nt * 16 * HBLD + kt * 16, HBLD);
                    wmma::mma_sync(fc, fa, fb, fc);
                }
                store_relu_half(h2b + mt * 16 * H2LD2 + nt * 16, H2LD2, fc);
            }
        }
        __syncthreads();
        {
            int o = tid & 63;
#pragma unroll
            for (int pi = 0; pi < 2; ++pi) {
                int p = (tid >> 6) + pi * 4;
                float mx = 0.f;
#pragma unroll
                for (int r = 0; r < KNN; ++r)
                    mx = fmaxf(mx, __half2float(h2b[(p * KNN + r) * H2LD2 + o]));
                g_cat[(pt0 + p) * CCAT + 256 + co * 64 + o] = __float2half_rn(mx);
            }
        }
        __syncthreads();
    }
}

// ===================== Kernel 3: L5 tiled GEMM (wmma fp16, half operands in gmem) =====================
#define KC5   64
#define ALD5  72
#define TILEH (128 * ALD5)

__global__ __launch_bounds__(256, 2) void l5_kernel(float* __restrict__ out) {
    extern __shared__ half hsm[];
    half* bufA[2] = { hsm,         hsm + 2 * TILEH };
    half* bufB[2] = { hsm + TILEH, hsm + 3 * TILEH };

    const int tid = threadIdx.x, warp = tid >> 5;
    const int n0 = blockIdx.x * 128;
    const int o0 = blockIdx.y * 128;
    const int b  = blockIdx.z;
    const half* catg = g_cat + ((size_t)b * NPTS + n0) * CCAT;
    const half* wg   = g_w5h + (size_t)o0 * CCAT;
    const int wr = warp >> 2, wc = warp & 3;

    HCf fc[4][2];
#pragma unroll
    for (int i = 0; i < 4; ++i) { wmma::fill_fragment(fc[i][0], 0.f); wmma::fill_fragment(fc[i][1], 0.f); }

    // pure half copies: per chunk each matrix = 128 rows x 8 uint4
    auto stage = [&](int kc, int bi) {
        half* pa = bufA[bi]; half* pb = bufB[bi];
#pragma unroll
        for (int it = 0; it < 4; ++it) {
            int lin = tid + it * 256;
            int r = lin >> 3, q = lin & 7;        // q: uint4 index (8 halves)
            *(uint4*)(pa + r * ALD5 + q * 8) = *(const uint4*)(wg   + (size_t)r * CCAT + kc * KC5 + q * 8);
            *(uint4*)(pb + r * ALD5 + q * 8) = *(const uint4*)(catg + (size_t)r * CCAT + kc * KC5 + q * 8);
        }
    };

    stage(0, 0);
    __syncthreads();

    HA fa; HB fb;
    for (int kc = 0; kc < 8; ++kc) {
        const int cur = kc & 1;
        if (kc + 1 < 8) stage(kc + 1, cur ^ 1);
        const half* A = bufA[cur];
        const half* B = bufB[cur];
#pragma unroll
        for (int kt = 0; kt < 4; ++kt) {
#pragma unroll
            for (int j = 0; j < 2; ++j) {
                wmma::load_matrix_sync(fb, B + (wc * 32 + j * 16) * ALD5 + kt * 16, ALD5);
#pragma unroll
                for (int i = 0; i < 4; ++i) {
                    wmma::load_matrix_sync(fa, A + (wr * 64 + i * 16) * ALD5 + kt * 16, ALD5);
                    wmma::mma_sync(fc[i][j], fa, fb, fc[i][j]);
                }
            }
        }
        __syncthreads();
    }

    float* scratch = (float*)hsm;   // 128*132*4 = 67.6KB <= 72KB
#pragma unroll
    for (int i = 0; i < 4; ++i)
#pragma unroll
        for (int j = 0; j < 2; ++j)
            wmma::store_matrix_sync(scratch + (wr * 64 + i * 16) * 132 + wc * 32 + j * 16,
                                    fc[i][j], 132, wmma::mem_row_major);
    __syncthreads();

    for (int i = tid; i < 128 * 128; i += 256) {
        int o = i >> 7, n = i & 127;
        out[((size_t)b * EMB + o0 + o) * NPTS + n0 + n] = fmaxf(scratch[o * 132 + n], 0.f);
    }
}

// ===================== launch =====================
extern "C" void kernel_launch(void* const* d_in, const int* in_sizes, int n_in,
                              void* d_out, int out_size) {
    const float* x  = (const float*)d_in[0];
    const float* w1 = (const float*)d_in[1];
    const float* w2 = (const float*)d_in[2];
    const float* w3 = (const float*)d_in[3];
    const float* w4 = (const float*)d_in[4];
    const float* w5 = (const float*)d_in[5];
    float* out = (float*)d_out;

    const int knn_smem   = NPTS * sizeof(float4);                                       // 64 KB
    const int l1234_smem = (LROWS * HBLD + LROWS * H2LD2 + 128 * H2LD2) * sizeof(half); // ~85 KB
    const int l5_smem    = 4 * TILEH * sizeof(half);                                    // 72 KB
    cudaFuncSetAttribute(knn_kernel,   cudaFuncAttributeMaxDynamicSharedMemorySize, knn_smem);
    cudaFuncSetAttribute(l1234_kernel, cudaFuncAttributeMaxDynamicSharedMemorySize, l1234_smem);
    cudaFuncSetAttribute(l5_kernel,    cudaFuncAttributeMaxDynamicSharedMemorySize, l5_smem);

    wconv_kernel<<<(EMB * CCAT) / 1024, 256>>>(w5);
    knn_kernel<<<dim3(NPTS / 128, BATCH), 128, knn_smem>>>(x);
    l1234_kernel<<<(BATCH * NPTS) / LPTS, 256, l1234_smem>>>(x, w1, w2, w3, w4);
    l5_kernel<<<dim3(NPTS / 128, EMB / 128, BATCH), 256, l5_smem>>>(out);
}

// round 11
// speedup vs baseline: 1.3025x; 1.1350x over previous
#include <cuda_runtime.h>
#include <math_constants.h>
#include <mma.h>
#include <cuda_fp16.h>
#include <cstdint>

using namespace nvcuda;

#define BATCH 8
#define NPTS  4096
#define KNN   20
#define CIN   26
#define C1    64
#define C2    64
#define C3    128
#define C4    256
#define CCAT  512
#define EMB   512

__device__ int    g_idx[BATCH * NPTS * KNN];
__device__ __half g_cat[(size_t)BATCH * NPTS * CCAT];   // 32 MB
__device__ __half g_w2h[C2 * C2];
__device__ __half g_w3h[C3 * C2];
__device__ __half g_w4h[C4 * C3];
__device__ __half g_w5h[EMB * CCAT];

// ===================== Kernel 0: fp32 -> half weight convert =====================
__global__ __launch_bounds__(256) void wconv_kernel(const float* __restrict__ src,
                                                    __half* __restrict__ dst, int n) {
    int i = (blockIdx.x * 256 + threadIdx.x) * 4;
    if (i < n) {
        float4 v = *(const float4*)(src + i);
        *(half2*)(dst + i)     = __floats2half2_rn(v.x, v.y);
        *(half2*)(dst + i + 2) = __floats2half2_rn(v.z, v.w);
    }
}

// ===================== Kernel 1: exact 20-NN (1 thread/point, 4-wide scan) =====================
__global__ __launch_bounds__(128) void knn_kernel(const float* __restrict__ x) {
    extern __shared__ float4 xs[];   // 64KB
    const int b = blockIdx.y;
    const float* xb = x + (size_t)b * 3 * NPTS;
    for (int m = threadIdx.x; m < NPTS; m += blockDim.x) {
        float x0 = xb[m], x1 = xb[NPTS + m], x2 = xb[2 * NPTS + m];
        xs[m] = make_float4(x0, x1, x2, fmaf(x0, x0, fmaf(x1, x1, x2 * x2)));
    }
    __syncthreads();
    const int n = blockIdx.x * blockDim.x + threadIdx.x;
    float4 p = xs[n];
    const float a0 = -2.f * p.x, a1 = -2.f * p.y, a2 = -2.f * p.z;
    float bv[KNN]; int bi[KNN];
#pragma unroll
    for (int t = 0; t < KNN; ++t) { bv[t] = CUDART_INF_F; bi[t] = -1; }
#pragma unroll 2
    for (int m = 0; m < NPTS; m += 4) {
        float4 q0 = xs[m], q1 = xs[m + 1], q2 = xs[m + 2], q3 = xs[m + 3];
        float v0 = fmaf(a0, q0.x, fmaf(a1, q0.y, fmaf(a2, q0.z, q0.w)));
        float v1 = fmaf(a0, q1.x, fmaf(a1, q1.y, fmaf(a2, q1.z, q1.w)));
        float v2 = fmaf(a0, q2.x, fmaf(a1, q2.y, fmaf(a2, q2.z, q2.w)));
        float v3 = fmaf(a0, q3.x, fmaf(a1, q3.y, fmaf(a2, q3.z, q3.w)));
        float vm = fminf(fminf(v0, v1), fminf(v2, v3));
        if (vm < bv[KNN - 1]) {
#pragma unroll
            for (int j = 0; j < 4; ++j) {     // ascending j keeps top_k tie order
                float v = (j == 0) ? v0 : (j == 1) ? v1 : (j == 2) ? v2 : v3;
                if (v < bv[KNN - 1]) {
                    bool ins = true;
#pragma unroll
                    for (int t = KNN - 1; t >= 1; --t) {
                        bool sh = v < bv[t - 1];
                        if (sh)       { bv[t] = bv[t - 1]; bi[t] = bi[t - 1]; }
                        else if (ins) { bv[t] = v;         bi[t] = m + j; }
                        ins = sh;
                    }
                    if (ins) { bv[0] = v; bi[0] = m + j; }
                }
            }
        }
    }
    int* outp = g_idx + ((size_t)b * NPTS + n) * KNN;
#pragma unroll
    for (int t = 0; t < KNN; ++t) outp[t] = bi[t];
}

// ===================== Kernel 2: fused L1(scalar) + L2/L3/L4 (wmma fp16) =====================
#define LPTS 8
#define LROWS (LPTS * KNN)   // 160
#define HBLD 136             // halves
#define H2LD2 72             // halves

typedef wmma::fragment<wmma::matrix_a, 16, 16, 16, half, wmma::row_major> HA;
typedef wmma::fragment<wmma::matrix_b, 16, 16, 16, half, wmma::col_major> HB;
typedef wmma::fragment<wmma::accumulator, 16, 16, 16, float> HCf;
typedef wmma::fragment<wmma::accumulator, 16, 16, 16, half>  HCh;

__device__ __forceinline__ void store_relu_half(half* dst, int ld, HCf& cf) {
    HCh ch;
#pragma unroll
    for (int i = 0; i < cf.num_elements; ++i)
        ch.x[i] = __float2half_rn(fmaxf(cf.x[i], 0.f));
    wmma::store_matrix_sync(dst, ch, ld, wmma::mem_row_major);
}

__global__ __launch_bounds__(256, 2) void l1234_kernel(
    const float* __restrict__ x, const float* __restrict__ w1) {
    extern __shared__ half hsm[];
    half* hb   = hsm;                        // 160*136 (h1, then h3)
    half* h2b  = hb + LROWS * HBLD;          // 160*72 (h2 / h4-chunk)
    half* wbuf = h2b + LROWS * H2LD2;        // 9216 h (W2/W3/W4-chunk)
    __shared__ float W1t[CIN * C1];
    __shared__ float s_nbr[LPTS][KNN][3];
    __shared__ float s_dist[LPTS][KNN];
    __shared__ float s_xn[LPTS][3];

    const int tid = threadIdx.x, warp = tid >> 5;
    const size_t pt0 = (size_t)blockIdx.x * LPTS;

    for (int i = tid; i < CIN * C1; i += 256) { int o = i / CIN, c = i % CIN; W1t[c * C1 + o] = w1[i]; }
    {   // W2 stage: 64x64 halves = 512 uint4
        const uint4* s = (const uint4*)g_w2h;
#pragma unroll
        for (int i = tid; i < 512; i += 256) { int o = i >> 3, q = i & 7; *(uint4*)(wbuf + o * H2LD2 + q * 8) = s[i]; }
    }

    if (tid < LPTS * KNN) {
        int p = tid / KNN, k = tid % KNN;
        size_t pt = pt0 + p;
        int b = (int)(pt >> 12), n = (int)(pt & (NPTS - 1));
        const float* xb = x + (size_t)b * 3 * NPTS;
        int nb = g_idx[pt * KNN + k];
        float c0 = xb[n], c1 = xb[NPTS + n], c2 = xb[2 * NPTS + n];
        float n0 = xb[nb], n1 = xb[NPTS + nb], n2 = xb[2 * NPTS + nb];
        s_nbr[p][k][0] = n0; s_nbr[p][k][1] = n1; s_nbr[p][k][2] = n2;
        float d0 = n0 - c0, d1 = n1 - c1, d2 = n2 - c2;
        s_dist[p][k] = sqrtf(fmaf(d0, d0, fmaf(d1, d1, d2 * d2)) + 1e-12f);
        if (k < 3) s_xn[p][k] = xb[k * NPTS + n];
    }
    __syncthreads();

    // L1 scalar -> hb (half), x1 -> cat[0:64]
    {
        int o = tid & 63;
#pragma unroll
        for (int pi = 0; pi < 2; ++pi) {
            int p = (tid >> 6) + pi * 4;
            float base = 0.f;
#pragma unroll
            for (int d = 0; d < 3; ++d) base = fmaf(W1t[d * C1 + o], s_xn[p][d], base);
#pragma unroll
            for (int j = 0; j < KNN; ++j) base = fmaf(W1t[(6 + j) * C1 + o], s_dist[p][j], base);
            float wa = W1t[3 * C1 + o], wb = W1t[4 * C1 + o], wc = W1t[5 * C1 + o];
            float mx = 0.f;
#pragma unroll
            for (int k = 0; k < KNN; ++k) {
                float v = fmaf(wa, s_nbr[p][k][0], fmaf(wb, s_nbr[p][k][1], fmaf(wc, s_nbr[p][k][2], base)));
                v = fmaxf(v, 0.f);
                mx = fmaxf(mx, v);
                hb[(p * KNN + k) * HBLD + o] = __float2half_rn(v);
            }
            g_cat[(pt0 + p) * CCAT + o] = __float2half_rn(mx);
        }
    }
    __syncthreads();

    // L2: M=160,N=64,K=64 -> h2b
    {
        HA fa; HB fb; HCf fc;
        for (int t = warp; t < 40; t += 8) {
            int mt = t >> 2, nt = t & 3;
            wmma::fill_fragment(fc, 0.f);
#pragma unroll
            for (int kt = 0; kt < 4; ++kt) {
                wmma::load_matrix_sync(fa, hb + mt * 16 * HBLD + kt * 16, HBLD);
                wmma::load_matrix_sync(fb, wbuf + nt * 16 * H2LD2 + kt * 16, H2LD2);
                wmma::mma_sync(fc, fa, fb, fc);
            }
            store_relu_half(h2b + mt * 16 * H2LD2 + nt * 16, H2LD2, fc);
        }
    }
    __syncthreads();

    // x2 -> cat[64:128]
    {
        int o = tid & 63;
#pragma unroll
        for (int pi = 0; pi < 2; ++pi) {
            int p = (tid >> 6) + pi * 4;
            float mx = 0.f;
#pragma unroll
            for (int k = 0; k < KNN; ++k)
                mx = fmaxf(mx, __half2float(h2b[(p * KNN + k) * H2LD2 + o]));
            g_cat[(pt0 + p) * CCAT + 64 + o] = __float2half_rn(mx);
        }
    }
    __syncthreads();

    {   // W3 stage: 128x64 halves = 1024 uint4
        const uint4* s = (const uint4*)g_w3h;
#pragma unroll
        for (int i = tid; i < 1024; i += 256) { int o = i >> 3, q = i & 7; *(uint4*)(wbuf + o * H2LD2 + q * 8) = s[i]; }
    }
    __syncthreads();

    // L3: M=160,N=128,K=64 -> hb
    {
        HA fa; HB fb; HCf fc;
        for (int t = warp; t < 80; t += 8) {
            int mt = t >> 3, nt = t & 7;
            wmma::fill_fragment(fc, 0.f);
#pragma unroll
            for (int kt = 0; kt < 4; ++kt) {
                wmma::load_matrix_sync(fa, h2b + mt * 16 * H2LD2 + kt * 16, H2LD2);
                wmma::load_matrix_sync(fb, wbuf + nt * 16 * H2LD2 + kt * 16, H2LD2);
                wmma::mma_sync(fc, fa, fb, fc);
            }
            store_relu_half(hb + mt * 16 * HBLD + nt * 16, HBLD, fc);
        }
    }
    __syncthreads();

    // x3 -> cat[128:256]
    {
        int oc = tid & 127;
#pragma unroll
        for (int pi = 0; pi < 4; ++pi) {
            int p = (tid >> 7) + pi * 2;
            float mx = 0.f;
#pragma unroll
            for (int r = 0; r < KNN; ++r)
                mx = fmaxf(mx, __half2float(hb[(p * KNN + r) * HBLD + oc]));
            g_cat[(pt0 + p) * CCAT + 128 + oc] = __float2half_rn(mx);
        }
    }
    __syncthreads();

    // L4: M=160,N=256(4x64),K=128
    for (int co = 0; co < 4; ++co) {
        {   // W4 chunk stage: 64 rows x 128 cols = 1024 uint4
            const uint4* s = (const uint4*)(g_w4h + (size_t)co * 64 * 128);
#pragma unroll
            for (int i = tid; i < 1024; i += 256) { int o = i >> 4, q = i & 15; *(uint4*)(wbuf + o * HBLD + q * 8) = s[i]; }
        }
        __syncthreads();
        {
            HA fa; HB fb; HCf fc;
            for (int t = warp; t < 40; t += 8) {
                int mt = t >> 2, nt = t & 3;
                wmma::fill_fragment(fc, 0.f);
#pragma unroll
                for (int kt = 0; kt < 8; ++kt) {
                    wmma::load_matrix_sync(fa, hb + mt * 16 * HBLD + kt * 16, HBLD);
                    wmma::load_matrix_sync(fb, wbuf + nt * 16 * HBLD + kt * 16, HBLD);
                    wmma::mma_sync(fc, fa, fb, fc);
                }
                store_relu_half(h2b + mt * 16 * H2LD2 + nt * 16, H2LD2, fc);
            }
        }
        __syncthreads();
        {
            int o = tid & 63;
#pragma unroll
            for (int pi = 0; pi < 2; ++pi) {
                int p = (tid >> 6) + pi * 4;
                float mx = 0.f;
#pragma unroll
                for (int r = 0; r < KNN; ++r)
                    mx = fmaxf(mx, __half2float(h2b[(p * KNN + r) * H2LD2 + o]));
                g_cat[(pt0 + p) * CCAT + 256 + co * 64 + o] = __float2half_rn(mx);
            }
        }
        __syncthreads();
    }
}

// ===================== Kernel 3: L5 tiled GEMM (wmma fp16) =====================
#define KC5   64
#define ALD5  72
#define TILEH (128 * ALD5)

__global__ __launch_bounds__(256, 2) void l5_kernel(float* __restrict__ out) {
    extern __shared__ half hsm[];
    half* bufA[2] = { hsm,         hsm + 2 * TILEH };
    half* bufB[2] = { hsm + TILEH, hsm + 3 * TILEH };

    const int tid = threadIdx.x, warp = tid >> 5;
    const int n0 = blockIdx.x * 128;
    const int o0 = blockIdx.y * 128;
    const int b  = blockIdx.z;
    const half* catg = g_cat + ((size_t)b * NPTS + n0) * CCAT;
    const half* wg   = g_w5h + (size_t)o0 * CCAT;
    const int wr = warp >> 2, wc = warp & 3;

    HCf fc[4][2];
#pragma unroll
    for (int i = 0; i < 4; ++i) { wmma::fill_fragment(fc[i][0], 0.f); wmma::fill_fragment(fc[i][1], 0.f); }

    auto stage = [&](int kc, int bi) {
        half* pa = bufA[bi]; half* pb = bufB[bi];
#pragma unroll
        for (int it = 0; it < 4; ++it) {
            int lin = tid + it * 256;
            int r = lin >> 3, q = lin & 7;
            *(uint4*)(pa + r * ALD5 + q * 8) = *(const uint4*)(wg   + (size_t)r * CCAT + kc * KC5 + q * 8);
            *(uint4*)(pb + r * ALD5 + q * 8) = *(const uint4*)(catg + (size_t)r * CCAT + kc * KC5 + q * 8);
        }
    };

    stage(0, 0);
    __syncthreads();

    HA fa; HB fb;
    for (int kc = 0; kc < 8; ++kc) {
        const int cur = kc & 1;
        if (kc + 1 < 8) stage(kc + 1, cur ^ 1);
        const half* A = bufA[cur];
        const half* B = bufB[cur];
#pragma unroll
        for (int kt = 0; kt < 4; ++kt) {
#pragma unroll
            for (int j = 0; j < 2; ++j) {
                wmma::load_matrix_sync(fb, B + (wc * 32 + j * 16) * ALD5 + kt * 16, ALD5);
#pragma unroll
                for (int i = 0; i < 4; ++i) {
                    wmma::load_matrix_sync(fa, A + (wr * 64 + i * 16) * ALD5 + kt * 16, ALD5);
                    wmma::mma_sync(fc[i][j], fa, fb, fc[i][j]);
                }
            }
        }
        __syncthreads();
    }

    float* scratch = (float*)hsm;
#pragma unroll
    for (int i = 0; i < 4; ++i)
#pragma unroll
        for (int j = 0; j < 2; ++j)
            wmma::store_matrix_sync(scratch + (wr * 64 + i * 16) * 132 + wc * 32 + j * 16,
                                    fc[i][j], 132, wmma::mem_row_major);
    __syncthreads();

    for (int i = tid; i < 128 * 128; i += 256) {
        int o = i >> 7, n = i & 127;
        out[((size_t)b * EMB + o0 + o) * NPTS + n0 + n] = fmaxf(scratch[o * 132 + n], 0.f);
    }
}

// ===================== launch =====================
extern "C" void kernel_launch(void* const* d_in, const int* in_sizes, int n_in,
                              void* d_out, int out_size) {
    const float* x  = (const float*)d_in[0];
    const float* w1 = (const float*)d_in[1];
    const float* w2 = (const float*)d_in[2];
    const float* w3 = (const float*)d_in[3];
    const float* w4 = (const float*)d_in[4];
    const float* w5 = (const float*)d_in[5];
    float* out = (float*)d_out;

    const int knn_smem   = NPTS * sizeof(float4);                                       // 64 KB
    const int l1234_smem = (LROWS * HBLD + LROWS * H2LD2 + 128 * H2LD2) * sizeof(half); // ~85 KB
    const int l5_smem    = 4 * TILEH * sizeof(half);                                    // 72 KB
    cudaFuncSetAttribute(knn_kernel,   cudaFuncAttributeMaxDynamicSharedMemorySize, knn_smem);
    cudaFuncSetAttribute(l1234_kernel, cudaFuncAttributeMaxDynamicSharedMemorySize, l1234_smem);
    cudaFuncSetAttribute(l5_kernel,    cudaFuncAttributeMaxDynamicSharedMemorySize, l5_smem);

    __half *d_w2h, *d_w3h, *d_w4h, *d_w5h;
    cudaGetSymbolAddress((void**)&d_w2h, g_w2h);
    cudaGetSymbolAddress((void**)&d_w3h, g_w3h);
    cudaGetSymbolAddress((void**)&d_w4h, g_w4h);
    cudaGetSymbolAddress((void**)&d_w5h, g_w5h);

    wconv_kernel<<<(C2 * C2 + 1023) / 1024, 256>>>(w2, d_w2h, C2 * C2);
    wconv_kernel<<<(C3 * C2 + 1023) / 1024, 256>>>(w3, d_w3h, C3 * C2);
    wconv_kernel<<<(C4 * C3 + 1023) / 1024, 256>>>(w4, d_w4h, C4 * C3);
    wconv_kernel<<<(EMB * CCAT + 1023) / 1024, 256>>>(w5, d_w5h, EMB * CCAT);
    knn_kernel<<<dim3(NPTS / 128, BATCH), 128, knn_smem>>>(x);
    l1234_kernel<<<(BATCH * NPTS) / LPTS, 256, l1234_smem>>>(x, w1);
    l5_kernel<<<dim3(NPTS / 128, EMB / 128, BATCH), 256, l5_smem>>>(out);
}

// round 12
// speedup vs baseline: 1.6734x; 1.2848x over previous
#include <cuda_runtime.h>
#include <math_constants.h>
#include <mma.h>
#include <cuda_fp16.h>
#include <cstdint>

using namespace nvcuda;

#define BATCH 8
#define NPTS  4096
#define KNN   20
#define CIN   26
#define C1    64
#define C2    64
#define C3    128
#define C4    256
#define CCAT  512
#define EMB   512

__device__ int    g_idx[BATCH * NPTS * KNN];
__device__ __half g_cat[(size_t)BATCH * NPTS * CCAT];   // 32 MB
__device__ __half g_w2h[C2 * C2];
__device__ __half g_w3h[C3 * C2];
__device__ __half g_w4h[C4 * C3];
__device__ __half g_w5h[EMB * CCAT];

// ===================== Kernel 0: all weights fp32 -> half (one launch) =====================
#define W2N (C2 * C2)          // 4096
#define W3N (C3 * C2)          // 8192
#define W4N (C4 * C3)          // 32768
#define W5N (EMB * CCAT)       // 262144
__global__ __launch_bounds__(256) void wconv_all(
    const float* __restrict__ w2, const float* __restrict__ w3,
    const float* __restrict__ w4, const float* __restrict__ w5) {
    int i = (blockIdx.x * 256 + threadIdx.x) * 4;
    const float* src; __half* dst; int off;
    if (i < W2N)                     { src = w2; dst = g_w2h; off = 0; }
    else if (i < W2N + W3N)          { src = w3; dst = g_w3h; off = W2N; }
    else if (i < W2N + W3N + W4N)    { src = w4; dst = g_w4h; off = W2N + W3N; }
    else                             { src = w5; dst = g_w5h; off = W2N + W3N + W4N; }
    int j = i - off;
    float4 v = *(const float4*)(src + j);
    *(half2*)(dst + j)     = __floats2half2_rn(v.x, v.y);
    *(half2*)(dst + j + 2) = __floats2half2_rn(v.z, v.w);
}

// ===================== Kernel 1: exact 20-NN — 1 point per WARP =====================
// Lane t (t<20) holds the rank-t (value,index) pair, ascending lexicographic.
// Inserts are warp-uniform shfl shifts: no divergent serial insertion path.
__global__ __launch_bounds__(512) void knn_kernel(const float* __restrict__ x) {
    extern __shared__ float4 xs[];   // 4096*16 = 64KB
    const int b = blockIdx.y;
    const float* xb = x + (size_t)b * 3 * NPTS;
    for (int m = threadIdx.x; m < NPTS; m += 512) {
        float x0 = xb[m], x1 = xb[NPTS + m], x2 = xb[2 * NPTS + m];
        xs[m] = make_float4(x0, x1, x2, fmaf(x0, x0, fmaf(x1, x1, x2 * x2)));
    }
    __syncthreads();
    const int warp = threadIdx.x >> 5, lane = threadIdx.x & 31;
    const int n = blockIdx.x * 16 + warp;
    float4 p = xs[n];
    const float a0 = -2.f * p.x, a1 = -2.f * p.y, a2 = -2.f * p.z;

    float bv = CUDART_INF_F;  int bi = 0x7FFFFFFF;   // distributed list
    float t19 = CUDART_INF_F; int ti19 = 0x7FFFFFFF; // lane-19 threshold (replicated)

    for (int it = 0; it < NPTS / 32; ++it) {
        const int m = it * 32 + lane;
        float4 q = xs[m];
        float v = fmaf(a0, q.x, fmaf(a1, q.y, fmaf(a2, q.z, q.w)));
        unsigned processed = 0;
        while (true) {
            bool qf = (v < t19) || (v == t19 && m < ti19);
            unsigned mask = __ballot_sync(0xffffffffu, qf) & ~processed;
            if (!mask) break;
            int src = __ffs(mask) - 1;
            processed |= (1u << src);
            float vv = __shfl_sync(0xffffffffu, v, src);
            int   ii = __shfl_sync(0xffffffffu, m, src);
            bool pr = (vv < bv) || (vv == bv && ii < bi);   // suffix of lanes (list sorted)
            unsigned pm = __ballot_sync(0xffffffffu, pr);
            int pos = __ffs(pm) - 1;
            float uv = __shfl_up_sync(0xffffffffu, bv, 1);
            int   ui = __shfl_up_sync(0xffffffffu, bi, 1);
            if (pr) { bv = (lane == pos) ? vv : uv; bi = (lane == pos) ? ii : ui; }
            t19  = __shfl_sync(0xffffffffu, bv, 19);
            ti19 = __shfl_sync(0xffffffffu, bi, 19);
        }
    }
    if (lane < KNN)
        g_idx[((size_t)b * NPTS + n) * KNN + lane] = bi;
}

// ===================== Kernel 2: fused L1(scalar) + L2/L3/L4 (wmma fp16) =====================
#define LPTS 8
#define LROWS (LPTS * KNN)   // 160
#define HBLD 136             // halves
#define H2LD2 72             // halves

typedef wmma::fragment<wmma::matrix_a, 16, 16, 16, half, wmma::row_major> HA;
typedef wmma::fragment<wmma::matrix_b, 16, 16, 16, half, wmma::col_major> HB;
typedef wmma::fragment<wmma::accumulator, 16, 16, 16, float> HCf;
typedef wmma::fragment<wmma::accumulator, 16, 16, 16, half>  HCh;

__device__ __forceinline__ void store_relu_half(half* dst, int ld, HCf& cf) {
    HCh ch;
#pragma unroll
    for (int i = 0; i < cf.num_elements; ++i)
        ch.x[i] = __float2half_rn(fmaxf(cf.x[i], 0.f));
    wmma::store_matrix_sync(dst, ch, ld, wmma::mem_row_major);
}

__global__ __launch_bounds__(256, 2) void l1234_kernel(
    const float* __restrict__ x, const float* __restrict__ w1) {
    extern __shared__ half hsm[];
    half* hb   = hsm;                        // 160*136 (h1, then h3)
    half* h2b  = hb + LROWS * HBLD;          // 160*72 (h2 / h4-chunk)
    half* wbuf = h2b + LROWS * H2LD2;        // 9216 h (W2/W3/W4-chunk)
    __shared__ float W1t[CIN * C1];
    __shared__ float s_nbr[LPTS][KNN][3];
    __shared__ float s_dist[LPTS][KNN];
    __shared__ float s_xn[LPTS][3];

    const int tid = threadIdx.x, warp = tid >> 5;
    const size_t pt0 = (size_t)blockIdx.x * LPTS;

    for (int i = tid; i < CIN * C1; i += 256) { int o = i / CIN, c = i % CIN; W1t[c * C1 + o] = w1[i]; }
    {   // W2 stage
        const uint4* s = (const uint4*)g_w2h;
#pragma unroll
        for (int i = tid; i < 512; i += 256) { int o = i >> 3, q = i & 7; *(uint4*)(wbuf + o * H2LD2 + q * 8) = s[i]; }
    }

    if (tid < LPTS * KNN) {
        int p = tid / KNN, k = tid % KNN;
        size_t pt = pt0 + p;
        int b = (int)(pt >> 12), n = (int)(pt & (NPTS - 1));
        const float* xb = x + (size_t)b * 3 * NPTS;
        int nb = g_idx[pt * KNN + k];
        float c0 = xb[n], c1 = xb[NPTS + n], c2 = xb[2 * NPTS + n];
        float n0 = xb[nb], n1 = xb[NPTS + nb], n2 = xb[2 * NPTS + nb];
        s_nbr[p][k][0] = n0; s_nbr[p][k][1] = n1; s_nbr[p][k][2] = n2;
        float d0 = n0 - c0, d1 = n1 - c1, d2 = n2 - c2;
        s_dist[p][k] = sqrtf(fmaf(d0, d0, fmaf(d1, d1, d2 * d2)) + 1e-12f);
        if (k < 3) s_xn[p][k] = xb[k * NPTS + n];
    }
    __syncthreads();

    // L1 scalar -> hb (half), x1 -> cat[0:64]
    {
        int o = tid & 63;
#pragma unroll
        for (int pi = 0; pi < 2; ++pi) {
            int p = (tid >> 6) + pi * 4;
            float base = 0.f;
#pragma unroll
            for (int d = 0; d < 3; ++d) base = fmaf(W1t[d * C1 + o], s_xn[p][d], base);
#pragma unroll
            for (int j = 0; j < KNN; ++j) base = fmaf(W1t[(6 + j) * C1 + o], s_dist[p][j], base);
            float wa = W1t[3 * C1 + o], wb = W1t[4 * C1 + o], wc = W1t[5 * C1 + o];
            float mx = 0.f;
#pragma unroll
            for (int k = 0; k < KNN; ++k) {
                float v = fmaf(wa, s_nbr[p][k][0], fmaf(wb, s_nbr[p][k][1], fmaf(wc, s_nbr[p][k][2], base)));
                v = fmaxf(v, 0.f);
                mx = fmaxf(mx, v);
                hb[(p * KNN + k) * HBLD + o] = __float2half_rn(v);
            }
            g_cat[(pt0 + p) * CCAT + o] = __float2half_rn(mx);
        }
    }
    __syncthreads();

    // L2: M=160,N=64,K=64 -> h2b
    {
        HA fa; HB fb; HCf fc;
        for (int t = warp; t < 40; t += 8) {
            int mt = t >> 2, nt = t & 3;
            wmma::fill_fragment(fc, 0.f);
#pragma unroll
            for (int kt = 0; kt < 4; ++kt) {
                wmma::load_matrix_sync(fa, hb + mt * 16 * HBLD + kt * 16, HBLD);
                wmma::load_matrix_sync(fb, wbuf + nt * 16 * H2LD2 + kt * 16, H2LD2);
                wmma::mma_sync(fc, fa, fb, fc);
            }
            store_relu_half(h2b + mt * 16 * H2LD2 + nt * 16, H2LD2, fc);
        }
    }
    __syncthreads();

    // x2 -> cat[64:128]
    {
        int o = tid & 63;
#pragma unroll
        for (int pi = 0; pi < 2; ++pi) {
            int p = (tid >> 6) + pi * 4;
            float mx = 0.f;
#pragma unroll
            for (int k = 0; k < KNN; ++k)
                mx = fmaxf(mx, __half2float(h2b[(p * KNN + k) * H2LD2 + o]));
            g_cat[(pt0 + p) * CCAT + 64 + o] = __float2half_rn(mx);
        }
    }
    __syncthreads();

    {   // W3 stage
        const uint4* s = (const uint4*)g_w3h;
#pragma unroll
        for (int i = tid; i < 1024; i += 256) { int o = i >> 3, q = i & 7; *(uint4*)(wbuf + o * H2LD2 + q * 8) = s[i]; }
    }
    __syncthreads();

    // L3: M=160,N=128,K=64 -> hb
    {
        HA fa; HB fb; HCf fc;
        for (int t = warp; t < 80; t += 8) {
            int mt = t >> 3, nt = t & 7;
            wmma::fill_fragment(fc, 0.f);
#pragma unroll
            for (int kt = 0; kt < 4; ++kt) {
                wmma::load_matrix_sync(fa, h2b + mt * 16 * H2LD2 + kt * 16, H2LD2);
                wmma::load_matrix_sync(fb, wbuf + nt * 16 * H2LD2 + kt * 16, H2LD2);
                wmma::mma_sync(fc, fa, fb, fc);
            }
            store_relu_half(hb + mt * 16 * HBLD + nt * 16, HBLD, fc);
        }
    }
    __syncthreads();

    // x3 -> cat[128:256]
    {
        int oc = tid & 127;
#pragma unroll
        for (int pi = 0; pi < 4; ++pi) {
            int p = (tid >> 7) + pi * 2;
            float mx = 0.f;
#pragma unroll
            for (int r = 0; r < KNN; ++r)
                mx = fmaxf(mx, __half2float(hb[(p * KNN + r) * HBLD + oc]));
            g_cat[(pt0 + p) * CCAT + 128 + oc] = __float2half_rn(mx);
        }
    }
    __syncthreads();

    // L4: M=160,N=256(4x64),K=128
    for (int co = 0; co < 4; ++co) {
        {
            const uint4* s = (const uint4*)(g_w4h + (size_t)co * 64 * 128);
#pragma unroll
            for (int i = tid; i < 1024; i += 256) { int o = i >> 4, q = i & 15; *(uint4*)(wbuf + o * HBLD + q * 8) = s[i]; }
        }
        __syncthreads();
        {
            HA fa; HB fb; HCf fc;
            for (int t = warp; t < 40; t += 8) {
                int mt = t >> 2, nt = t & 3;
                wmma::fill_fragment(fc, 0.f);
#pragma unroll
                for (int kt = 0; kt < 8; ++kt) {
                    wmma::load_matrix_sync(fa, hb + mt * 16 * HBLD + kt * 16, HBLD);
                    wmma::load_matrix_sync(fb, wbuf + nt * 16 * HBLD + kt * 16, HBLD);
                    wmma::mma_sync(fc, fa, fb, fc);
                }
                store_relu_half(h2b + mt * 16 * H2LD2 + nt * 16, H2LD2, fc);
            }
        }
        __syncthreads();
        {
            int o = tid & 63;
#pragma unroll
            for (int pi = 0; pi < 2; ++pi) {
                int p = (tid >> 6) + pi * 4;
                float mx = 0.f;
#pragma unroll
                for (int r = 0; r < KNN; ++r)
                    mx = fmaxf(mx, __half2float(h2b[(p * KNN + r) * H2LD2 + o]));
                g_cat[(pt0 + p) * CCAT + 256 + co * 64 + o] = __float2half_rn(mx);
            }
        }
        __syncthreads();
    }
}

// ===================== Kernel 3: L5 tiled GEMM (wmma fp16) =====================
#define KC5   64
#define ALD5  72
#define TILEH (128 * ALD5)

__global__ __launch_bounds__(256, 2) void l5_kernel(float* __restrict__ out) {
    extern __shared__ half hsm[];
    half* bufA[2] = { hsm,         hsm + 2 * TILEH };
    half* bufB[2] = { hsm + TILEH, hsm + 3 * TILEH };

    const int tid = threadIdx.x, warp = tid >> 5;
    const int n0 = blockIdx.x * 128;
    const int o0 = blockIdx.y * 128;
    const int b  = blockIdx.z;
    const half* catg = g_cat + ((size_t)b * NPTS + n0) * CCAT;
    const half* wg   = g_w5h + (size_t)o0 * CCAT;
    const int wr = warp >> 2, wc = warp & 3;

    HCf fc[4][2];
#pragma unroll
    for (int i = 0; i < 4; ++i) { wmma::fill_fragment(fc[i][0], 0.f); wmma::fill_fragment(fc[i][1], 0.f); }

    auto stage = [&](int kc, int bi) {
        half* pa = bufA[bi]; half* pb = bufB[bi];
#pragma unroll
        for (int it = 0; it < 4; ++it) {
            int lin = tid + it * 256;
            int r = lin >> 3, q = lin & 7;
            *(uint4*)(pa + r * ALD5 + q * 8) = *(const uint4*)(wg   + (size_t)r * CCAT + kc * KC5 + q * 8);
            *(uint4*)(pb + r * ALD5 + q * 8) = *(const uint4*)(catg + (size_t)r * CCAT + kc * KC5 + q * 8);
        }
    };

    stage(0, 0);
    __syncthreads();

    HA fa; HB fb;
    for (int kc = 0; kc < 8; ++kc) {
        const int cur = kc & 1;
        if (kc + 1 < 8) stage(kc + 1, cur ^ 1);
        const half* A = bufA[cur];
        const half* B = bufB[cur];
#pragma unroll
        for (int kt = 0; kt < 4; ++kt) {
#pragma unroll
            for (int j = 0; j < 2; ++j) {
                wmma::load_matrix_sync(fb, B + (wc * 32 + j * 16) * ALD5 + kt * 16, ALD5);
#pragma unroll
                for (int i = 0; i < 4; ++i) {
                    wmma::load_matrix_sync(fa, A + (wr * 64 + i * 16) * ALD5 + kt * 16, ALD5);
                    wmma::mma_sync(fc[i][j], fa, fb, fc[i][j]);
                }
            }
        }
        __syncthreads();
    }

    float* scratch = (float*)hsm;
#pragma unroll
    for (int i = 0; i < 4; ++i)
#pragma unroll
        for (int j = 0; j < 2; ++j)
            wmma::store_matrix_sync(scratch + (wr * 64 + i * 16) * 132 + wc * 32 + j * 16,
                                    fc[i][j], 132, wmma::mem_row_major);
    __syncthreads();

    for (int i = tid; i < 128 * 128; i += 256) {
        int o = i >> 7, n = i & 127;
        out[((size_t)b * EMB + o0 + o) * NPTS + n0 + n] = fmaxf(scratch[o * 132 + n], 0.f);
    }
}

// ===================== launch =====================
extern "C" void kernel_launch(void* const* d_in, const int* in_sizes, int n_in,
                              void* d_out, int out_size) {
    const float* x  = (const float*)d_in[0];
    const float* w1 = (const float*)d_in[1];
    const float* w2 = (const float*)d_in[2];
    const float* w3 = (const float*)d_in[3];
    const float* w4 = (const float*)d_in[4];
    const float* w5 = (const float*)d_in[5];
    float* out = (float*)d_out;

    const int knn_smem   = NPTS * sizeof(float4);                                       // 64 KB
    const int l1234_smem = (LROWS * HBLD + LROWS * H2LD2 + 128 * H2LD2) * sizeof(half); // ~85 KB
    const int l5_smem    = 4 * TILEH * sizeof(half);                                    // 72 KB
    cudaFuncSetAttribute(knn_kernel,   cudaFuncAttributeMaxDynamicSharedMemorySize, knn_smem);
    cudaFuncSetAttribute(l1234_kernel, cudaFuncAttributeMaxDynamicSharedMemorySize, l1234_smem);
    cudaFuncSetAttribute(l5_kernel,    cudaFuncAttributeMaxDynamicSharedMemorySize, l5_smem);

    wconv_all<<<(W2N + W3N + W4N + W5N) / 1024, 256>>>(w2, w3, w4, w5);
    knn_kernel<<<dim3(NPTS / 16, BATCH), 512, knn_smem>>>(x);
    l1234_kernel<<<(BATCH * NPTS) / LPTS, 256, l1234_smem>>>(x, w1);
    l5_kernel<<<dim3(NPTS / 128, EMB / 128, BATCH), 256, l5_smem>>>(out);
}

// round 13
// speedup vs baseline: 1.8715x; 1.1184x over previous
#include <cuda_runtime.h>
#include <math_constants.h>
#include <mma.h>
#include <cuda_fp16.h>
#include <cstdint>

using namespace nvcuda;

#define BATCH 8
#define NPTS  4096
#define KNN   20
#define CIN   26
#define C1    64
#define C2    64
#define C3    128
#define C4    256
#define CCAT  512
#define EMB   512

__device__ int    g_idx[BATCH * NPTS * KNN];
__device__ __half g_cat[(size_t)BATCH * NPTS * CCAT];   // 32 MB
__device__ __half g_w2h[C2 * C2];
__device__ __half g_w3h[C3 * C2];
__device__ __half g_w4h[C4 * C3];
__device__ __half g_w5h[EMB * CCAT];

// ===================== Kernel 0: all weights fp32 -> half =====================
#define W2N (C2 * C2)
#define W3N (C3 * C2)
#define W4N (C4 * C3)
#define W5N (EMB * CCAT)
__global__ __launch_bounds__(256) void wconv_all(
    const float* __restrict__ w2, const float* __restrict__ w3,
    const float* __restrict__ w4, const float* __restrict__ w5) {
    int i = (blockIdx.x * 256 + threadIdx.x) * 4;
    const float* src; __half* dst; int off;
    if (i < W2N)                  { src = w2; dst = g_w2h; off = 0; }
    else if (i < W2N + W3N)       { src = w3; dst = g_w3h; off = W2N; }
    else if (i < W2N + W3N + W4N) { src = w4; dst = g_w4h; off = W2N + W3N; }
    else                          { src = w5; dst = g_w5h; off = W2N + W3N + W4N; }
    int j = i - off;
    float4 v = *(const float4*)(src + j);
    *(half2*)(dst + j)     = __floats2half2_rn(v.x, v.y);
    *(half2*)(dst + j + 2) = __floats2half2_rn(v.z, v.w);
}

// ===================== Kernel 1: exact 20-NN — 1 point per WARP =====================
__global__ __launch_bounds__(512) void knn_kernel(const float* __restrict__ x) {
    extern __shared__ float4 xs[];
    const int b = blockIdx.y;
    const float* xb = x + (size_t)b * 3 * NPTS;
    for (int m = threadIdx.x; m < NPTS; m += 512) {
        float x0 = xb[m], x1 = xb[NPTS + m], x2 = xb[2 * NPTS + m];
        xs[m] = make_float4(x0, x1, x2, fmaf(x0, x0, fmaf(x1, x1, x2 * x2)));
    }
    __syncthreads();
    const int warp = threadIdx.x >> 5, lane = threadIdx.x & 31;
    const int n = blockIdx.x * 16 + warp;
    float4 p = xs[n];
    const float a0 = -2.f * p.x, a1 = -2.f * p.y, a2 = -2.f * p.z;

    float bv = CUDART_INF_F;  int bi = 0x7FFFFFFF;
    float t19 = CUDART_INF_F; int ti19 = 0x7FFFFFFF;

    for (int it = 0; it < NPTS / 32; ++it) {
        const int m = it * 32 + lane;
        float4 q = xs[m];
        float v = fmaf(a0, q.x, fmaf(a1, q.y, fmaf(a2, q.z, q.w)));
        unsigned processed = 0;
        while (true) {
            bool qf = (v < t19) || (v == t19 && m < ti19);
            unsigned mask = __ballot_sync(0xffffffffu, qf) & ~processed;
            if (!mask) break;
            int src = __ffs(mask) - 1;
            processed |= (1u << src);
            float vv = __shfl_sync(0xffffffffu, v, src);
            int   ii = __shfl_sync(0xffffffffu, m, src);
            bool pr = (vv < bv) || (vv == bv && ii < bi);
            unsigned pm = __ballot_sync(0xffffffffu, pr);
            int pos = __ffs(pm) - 1;
            float uv = __shfl_up_sync(0xffffffffu, bv, 1);
            int   ui = __shfl_up_sync(0xffffffffu, bi, 1);
            if (pr) { bv = (lane == pos) ? vv : uv; bi = (lane == pos) ? ii : ui; }
            t19  = __shfl_sync(0xffffffffu, bv, 19);
            ti19 = __shfl_sync(0xffffffffu, bi, 19);
        }
    }
    if (lane < KNN)
        g_idx[((size_t)b * NPTS + n) * KNN + lane] = bi;
}

// ===================== Kernel 2: fused L1(scalar) + L2/L3/L4 (wmma fp16, fragment reuse) =====================
#define LPTS 8
#define LROWS (LPTS * KNN)   // 160
#define HBLD 136
#define H2LD2 72

typedef wmma::fragment<wmma::matrix_a, 16, 16, 16, half, wmma::row_major> HA;
typedef wmma::fragment<wmma::matrix_b, 16, 16, 16, half, wmma::col_major> HB;
typedef wmma::fragment<wmma::accumulator, 16, 16, 16, float> HCf;
typedef wmma::fragment<wmma::accumulator, 16, 16, 16, half>  HCh;

__device__ __forceinline__ void store_relu_half(half* dst, int ld, HCf& cf) {
    HCh ch;
#pragma unroll
    for (int i = 0; i < cf.num_elements; ++i)
        ch.x[i] = __float2half_rn(fmaxf(cf.x[i], 0.f));
    wmma::store_matrix_sync(dst, ch, ld, wmma::mem_row_major);
}

__global__ __launch_bounds__(256, 2) void l1234_kernel(
    const float* __restrict__ x, const float* __restrict__ w1) {
    extern __shared__ half hsm[];
    half* hb   = hsm;                        // 160*136 (h1, then h3)
    half* h2b  = hb + LROWS * HBLD;          // 160*72 (h2 / h4-chunk)
    half* wbuf = h2b + LROWS * H2LD2;        // 9216 h (W2/W3/W4-chunk)
    __shared__ float W1t[CIN * C1];
    __shared__ float s_nbr[LPTS][KNN][3];
    __shared__ float s_dist[LPTS][KNN];
    __shared__ float s_xn[LPTS][3];

    const int tid = threadIdx.x, warp = tid >> 5;
    const size_t pt0 = (size_t)blockIdx.x * LPTS;

    for (int i = tid; i < CIN * C1; i += 256) { int o = i / CIN, c = i % CIN; W1t[c * C1 + o] = w1[i]; }
    {   // W2 stage
        const uint4* s = (const uint4*)g_w2h;
#pragma unroll
        for (int i = tid; i < 512; i += 256) { int o = i >> 3, q = i & 7; *(uint4*)(wbuf + o * H2LD2 + q * 8) = s[i]; }
    }

    if (tid < LPTS * KNN) {
        int p = tid / KNN, k = tid % KNN;
        size_t pt = pt0 + p;
        int b = (int)(pt >> 12), n = (int)(pt & (NPTS - 1));
        const float* xb = x + (size_t)b * 3 * NPTS;
        int nb = g_idx[pt * KNN + k];
        float c0 = xb[n], c1 = xb[NPTS + n], c2 = xb[2 * NPTS + n];
        float n0 = xb[nb], n1 = xb[NPTS + nb], n2 = xb[2 * NPTS + nb];
        s_nbr[p][k][0] = n0; s_nbr[p][k][1] = n1; s_nbr[p][k][2] = n2;
        float d0 = n0 - c0, d1 = n1 - c1, d2 = n2 - c2;
        s_dist[p][k] = sqrtf(fmaf(d0, d0, fmaf(d1, d1, d2 * d2)) + 1e-12f);
        if (k < 3) s_xn[p][k] = xb[k * NPTS + n];
    }
    __syncthreads();

    // L1 scalar -> hb (half), x1 -> cat[0:64]
    {
        int o = tid & 63;
#pragma unroll
        for (int pi = 0; pi < 2; ++pi) {
            int p = (tid >> 6) + pi * 4;
            float base = 0.f;
#pragma unroll
            for (int d = 0; d < 3; ++d) base = fmaf(W1t[d * C1 + o], s_xn[p][d], base);
#pragma unroll
            for (int j = 0; j < KNN; ++j) base = fmaf(W1t[(6 + j) * C1 + o], s_dist[p][j], base);
            float wa = W1t[3 * C1 + o], wb = W1t[4 * C1 + o], wc = W1t[5 * C1 + o];
            float mx = 0.f;
#pragma unroll
            for (int k = 0; k < KNN; ++k) {
                float v = fmaf(wa, s_nbr[p][k][0], fmaf(wb, s_nbr[p][k][1], fmaf(wc, s_nbr[p][k][2], base)));
                v = fmaxf(v, 0.f);
                mx = fmaxf(mx, v);
                hb[(p * KNN + k) * HBLD + o] = __float2half_rn(v);
            }
            g_cat[(pt0 + p) * CCAT + o] = __float2half_rn(mx);
        }
    }
    __syncthreads();

    // L2: D(160x64) = h1 @ W2^T. warp: nt = w&3 (2 warps/nt), 5 mt each. fb reused.
    {
        const int nt = warp & 3, hf = warp >> 2;
        HA fa; HB fb; HCf fc[5];
#pragma unroll
        for (int i = 0; i < 5; ++i) wmma::fill_fragment(fc[i], 0.f);
#pragma unroll
        for (int kt = 0; kt < 4; ++kt) {
            wmma::load_matrix_sync(fb, wbuf + nt * 16 * H2LD2 + kt * 16, H2LD2);
#pragma unroll
            for (int i = 0; i < 5; ++i) {
                wmma::load_matrix_sync(fa, hb + (hf * 5 + i) * 16 * HBLD + kt * 16, HBLD);
                wmma::mma_sync(fc[i], fa, fb, fc[i]);
            }
        }
#pragma unroll
        for (int i = 0; i < 5; ++i)
            store_relu_half(h2b + (hf * 5 + i) * 16 * H2LD2 + nt * 16, H2LD2, fc[i]);
    }
    __syncthreads();

    // x2 -> cat[64:128]
    {
        int o = tid & 63;
#pragma unroll
        for (int pi = 0; pi < 2; ++pi) {
            int p = (tid >> 6) + pi * 4;
            float mx = 0.f;
#pragma unroll
            for (int k = 0; k < KNN; ++k)
                mx = fmaxf(mx, __half2float(h2b[(p * KNN + k) * H2LD2 + o]));
            g_cat[(pt0 + p) * CCAT + 64 + o] = __float2half_rn(mx);
        }
    }
    __syncthreads();

    {   // W3 stage
        const uint4* s = (const uint4*)g_w3h;
#pragma unroll
        for (int i = tid; i < 1024; i += 256) { int o = i >> 3, q = i & 7; *(uint4*)(wbuf + o * H2LD2 + q * 8) = s[i]; }
    }
    __syncthreads();

    // L3: D(160x128) = h2 @ W3^T. warp owns nt = w; 2 passes of 5 mt. fb reused.
    {
        HA fa; HB fb;
#pragma unroll
        for (int pass = 0; pass < 2; ++pass) {
            HCf fc[5];
#pragma unroll
            for (int i = 0; i < 5; ++i) wmma::fill_fragment(fc[i], 0.f);
#pragma unroll
            for (int kt = 0; kt < 4; ++kt) {
                wmma::load_matrix_sync(fb, wbuf + warp * 16 * H2LD2 + kt * 16, H2LD2);
#pragma unroll
                for (int i = 0; i < 5; ++i) {
                    wmma::load_matrix_sync(fa, h2b + (pass * 5 + i) * 16 * H2LD2 + kt * 16, H2LD2);
                    wmma::mma_sync(fc[i], fa, fb, fc[i]);
                }
            }
#pragma unroll
            for (int i = 0; i < 5; ++i)
                store_relu_half(hb + (pass * 5 + i) * 16 * HBLD + warp * 16, HBLD, fc[i]);
        }
    }
    __syncthreads();

    // x3 -> cat[128:256]
    {
        int oc = tid & 127;
#pragma unroll
        for (int pi = 0; pi < 4; ++pi) {
            int p = (tid >> 7) + pi * 2;
            float mx = 0.f;
#pragma unroll
            for (int r = 0; r < KNN; ++r)
                mx = fmaxf(mx, __half2float(hb[(p * KNN + r) * HBLD + oc]));
            g_cat[(pt0 + p) * CCAT + 128 + oc] = __float2half_rn(mx);
        }
    }
    __syncthreads();

    // L4: D(160x256) in 4 chunks of 64. warp: nt = w&3 (2 warps/nt), 5 mt. fb reused.
    for (int co = 0; co < 4; ++co) {
        {
            const uint4* s = (const uint4*)(g_w4h + (size_t)co * 64 * 128);
#pragma unroll
            for (int i = tid; i < 1024; i += 256) { int o = i >> 4, q = i & 15; *(uint4*)(wbuf + o * HBLD + q * 8) = s[i]; }
        }
        __syncthreads();
        {
            const int nt = warp & 3, hf = warp >> 2;
            HA fa; HB fb; HCf fc[5];
#pragma unroll
            for (int i = 0; i < 5; ++i) wmma::fill_fragment(fc[i], 0.f);
#pragma unroll
            for (int kt = 0; kt < 8; ++kt) {
                wmma::load_matrix_sync(fb, wbuf + nt * 16 * HBLD + kt * 16, HBLD);
#pragma unroll
                for (int i = 0; i < 5; ++i) {
                    wmma::load_matrix_sync(fa, hb + (hf * 5 + i) * 16 * HBLD + kt * 16, HBLD);
                    wmma::mma_sync(fc[i], fa, fb, fc[i]);
                }
            }
#pragma unroll
            for (int i = 0; i < 5; ++i)
                store_relu_half(h2b + (hf * 5 + i) * 16 * H2LD2 + nt * 16, H2LD2, fc[i]);
        }
        __syncthreads();
        {
            int o = tid & 63;
#pragma unroll
            for (int pi = 0; pi < 2; ++pi) {
                int p = (tid >> 6) + pi * 4;
                float mx = 0.f;
#pragma unroll
                for (int r = 0; r < KNN; ++r)
                    mx = fmaxf(mx, __half2float(h2b[(p * KNN + r) * H2LD2 + o]));
                g_cat[(pt0 + p) * CCAT + 256 + co * 64 + o] = __float2half_rn(mx);
            }
        }
        __syncthreads();
    }
}

// ===================== Kernel 3: L5 tiled GEMM (wmma fp16) =====================
#define KC5   64
#define ALD5  72
#define TILEH (128 * ALD5)

__global__ __launch_bounds__(256, 2) void l5_kernel(float* __restrict__ out) {
    extern __shared__ half hsm[];
    half* bufA[2] = { hsm,         hsm + 2 * TILEH };
    half* bufB[2] = { hsm + TILEH, hsm + 3 * TILEH };

    const int tid = threadIdx.x, warp = tid >> 5;
    const int n0 = blockIdx.x * 128;
    const int o0 = blockIdx.y * 128;
    const int b  = blockIdx.z;
    const half* catg = g_cat + ((size_t)b * NPTS + n0) * CCAT;
    const half* wg   = g_w5h + (size_t)o0 * CCAT;
    const int wr = warp >> 2, wc = warp & 3;

    HCf fc[4][2];
#pragma unroll
    for (int i = 0; i < 4; ++i) { wmma::fill_fragment(fc[i][0], 0.f); wmma::fill_fragment(fc[i][1], 0.f); }

    auto stage = [&](int kc, int bi) {
        half* pa = bufA[bi]; half* pb = bufB[bi];
#pragma unroll
        for (int it = 0; it < 4; ++it) {
            int lin = tid + it * 256;
            int r = lin >> 3, q = lin & 7;
            *(uint4*)(pa + r * ALD5 + q * 8) = *(const uint4*)(wg   + (size_t)r * CCAT + kc * KC5 + q * 8);
            *(uint4*)(pb + r * ALD5 + q * 8) = *(const uint4*)(catg + (size_t)r * CCAT + kc * KC5 + q * 8);
        }
    };

    stage(0, 0);
    __syncthreads();

    HA fa; HB fb;
    for (int kc = 0; kc < 8; ++kc) {
        const int cur = kc & 1;
        if (kc + 1 < 8) stage(kc + 1, cur ^ 1);
        const half* A = bufA[cur];
        const half* B = bufB[cur];
#pragma unroll
        for (int kt = 0; kt < 4; ++kt) {
#pragma unroll
            for (int j = 0; j < 2; ++j) {
                wmma::load_matrix_sync(fb, B + (wc * 32 + j * 16) * ALD5 + kt * 16, ALD5);
#pragma unroll
                for (int i = 0; i < 4; ++i) {
                    wmma::load_matrix_sync(fa, A + (wr * 64 + i * 16) * ALD5 + kt * 16, ALD5);
                    wmma::mma_sync(fc[i][j], fa, fb, fc[i][j]);
                }
            }
        }
        __syncthreads();
    }

    float* scratch = (float*)hsm;
#pragma unroll
    for (int i = 0; i < 4; ++i)
#pragma unroll
        for (int j = 0; j < 2; ++j)
            wmma::store_matrix_sync(scratch + (wr * 64 + i * 16) * 132 + wc * 32 + j * 16,
                                    fc[i][j], 132, wmma::mem_row_major);
    __syncthreads();

    for (int i = tid; i < 128 * 128; i += 256) {
        int o = i >> 7, n = i & 127;
        out[((size_t)b * EMB + o0 + o) * NPTS + n0 + n] = fmaxf(scratch[o * 132 + n], 0.f);
    }
}

// ===================== launch =====================
extern "C" void kernel_launch(void* const* d_in, const int* in_sizes, int n_in,
                              void* d_out, int out_size) {
    const float* x  = (const float*)d_in[0];
    const float* w1 = (const float*)d_in[1];
    const float* w2 = (const float*)d_in[2];
    const float* w3 = (const float*)d_in[3];
    const float* w4 = (const float*)d_in[4];
    const float* w5 = (const float*)d_in[5];
    float* out = (float*)d_out;

    const int knn_smem   = NPTS * sizeof(float4);
    const int l1234_smem = (LROWS * HBLD + LROWS * H2LD2 + 128 * H2LD2) * sizeof(half);
    const int l5_smem    = 4 * TILEH * sizeof(half);
    cudaFuncSetAttribute(knn_kernel,   cudaFuncAttributeMaxDynamicSharedMemorySize, knn_smem);
    cudaFuncSetAttribute(l1234_kernel, cudaFuncAttributeMaxDynamicSharedMemorySize, l1234_smem);
    cudaFuncSetAttribute(l5_kernel,    cudaFuncAttributeMaxDynamicSharedMemorySize, l5_smem);

    wconv_all<<<(W2N + W3N + W4N + W5N) / 1024, 256>>>(w2, w3, w4, w5);
    knn_kernel<<<dim3(NPTS / 16, BATCH), 512, knn_smem>>>(x);
    l1234_kernel<<<(BATCH * NPTS) / LPTS, 256, l1234_smem>>>(x, w1);
    l5_kernel<<<dim3(NPTS / 128, EMB / 128, BATCH), 256, l5_smem>>>(out);
}

// round 15
// speedup vs baseline: 1.9256x; 1.0289x over previous
#include <cuda_runtime.h>
#include <math_constants.h>
#include <mma.h>
#include <cuda_fp16.h>
#include <cstdint>

using namespace nvcuda;

#define BATCH 8
#define NPTS  4096
#define KNN   20
#define CIN   26
#define C1    64
#define C2    64
#define C3    128
#define C4    256
#define CCAT  512
#define EMB   512

__device__ int    g_idx[BATCH * NPTS * KNN];
__device__ __half g_cat[(size_t)BATCH * NPTS * CCAT];   // 32 MB
__device__ __half g_w2h[C2 * C2];
__device__ __half g_w3h[C3 * C2];
__device__ __half g_w4h[C4 * C3];
__device__ __half g_w5h[EMB * CCAT];

// ===================== Kernel 0: all weights fp32 -> half =====================
#define W2N (C2 * C2)
#define W3N (C3 * C2)
#define W4N (C4 * C3)
#define W5N (EMB * CCAT)
__global__ __launch_bounds__(256) void wconv_all(
    const float* __restrict__ w2, const float* __restrict__ w3,
    const float* __restrict__ w4, const float* __restrict__ w5) {
    int i = (blockIdx.x * 256 + threadIdx.x) * 4;
    const float* src; __half* dst; int off;
    if (i < W2N)                  { src = w2; dst = g_w2h; off = 0; }
    else if (i < W2N + W3N)       { src = w3; dst = g_w3h; off = W2N; }
    else if (i < W2N + W3N + W4N) { src = w4; dst = g_w4h; off = W2N + W3N; }
    else                          { src = w5; dst = g_w5h; off = W2N + W3N + W4N; }
    int j = i - off;
    float4 v = *(const float4*)(src + j);
    *(half2*)(dst + j)     = __floats2half2_rn(v.x, v.y);
    *(half2*)(dst + j + 2) = __floats2half2_rn(v.z, v.w);
}

// ===================== Kernel 1: exact 20-NN — 1 point per WARP =====================
__global__ __launch_bounds__(512) void knn_kernel(const float* __restrict__ x) {
    extern __shared__ float4 xs[];
    const int b = blockIdx.y;
    const float* xb = x + (size_t)b * 3 * NPTS;
    for (int m = threadIdx.x; m < NPTS; m += 512) {
        float x0 = xb[m], x1 = xb[NPTS + m], x2 = xb[2 * NPTS + m];
        xs[m] = make_float4(x0, x1, x2, fmaf(x0, x0, fmaf(x1, x1, x2 * x2)));
    }
    __syncthreads();
    const int warp = threadIdx.x >> 5, lane = threadIdx.x & 31;
    const int n = blockIdx.x * 16 + warp;
    float4 p = xs[n];
    const float a0 = -2.f * p.x, a1 = -2.f * p.y, a2 = -2.f * p.z;

    float bv = CUDART_INF_F;  int bi = 0x7FFFFFFF;
    float t19 = CUDART_INF_F; int ti19 = 0x7FFFFFFF;

    for (int it = 0; it < NPTS / 32; ++it) {
        const int m = it * 32 + lane;
        float4 q = xs[m];
        float v = fmaf(a0, q.x, fmaf(a1, q.y, fmaf(a2, q.z, q.w)));
        unsigned processed = 0;
        while (true) {
            bool qf = (v < t19) || (v == t19 && m < ti19);
            unsigned mask = __ballot_sync(0xffffffffu, qf) & ~processed;
            if (!mask) break;
            int src = __ffs(mask) - 1;
            processed |= (1u << src);
            float vv = __shfl_sync(0xffffffffu, v, src);
            int   ii = __shfl_sync(0xffffffffu, m, src);
            bool pr = (vv < bv) || (vv == bv && ii < bi);
            unsigned pm = __ballot_sync(0xffffffffu, pr);
            int pos = __ffs(pm) - 1;
            float uv = __shfl_up_sync(0xffffffffu, bv, 1);
            int   ui = __shfl_up_sync(0xffffffffu, bi, 1);
            if (pr) { bv = (lane == pos) ? vv : uv; bi = (lane == pos) ? ii : ui; }
            t19  = __shfl_sync(0xffffffffu, bv, 19);
            ti19 = __shfl_sync(0xffffffffu, bi, 19);
        }
    }
    if (lane < KNN)
        g_idx[((size_t)b * NPTS + n) * KNN + lane] = bi;
}

// ===================== Kernel 2: fused L1 + L2/L3/L4 (prefetch + merged epilogues) =====================
#define LPTS 8
#define LROWS (LPTS * KNN)   // 160
#define HBLD 136
#define H2LD2 72
#define WBH 9216             // halves per weight buffer

typedef wmma::fragment<wmma::matrix_a, 16, 16, 16, half, wmma::row_major> HA;
typedef wmma::fragment<wmma::matrix_b, 16, 16, 16, half, wmma::col_major> HB;
typedef wmma::fragment<wmma::accumulator, 16, 16, 16, float> HCf;
typedef wmma::fragment<wmma::accumulator, 16, 16, 16, half>  HCh;

__device__ __forceinline__ void store_relu_half(half* dst, int ld, HCf& cf) {
    HCh ch;
#pragma unroll
    for (int i = 0; i < cf.num_elements; ++i)
        ch.x[i] = __float2half_rn(fmaxf(cf.x[i], 0.f));
    wmma::store_matrix_sync(dst, ch, ld, wmma::mem_row_major);
}

__global__ __launch_bounds__(256, 2) void l1234_kernel(
    const float* __restrict__ x, const float* __restrict__ w1) {
    extern __shared__ half hsm[];
    half* hb  = hsm;                 // 160*136 = 21760 (h1, then h3)
    half* h2b = hb + LROWS * HBLD;   // 160*72  = 11520 (h2 / l4-chunk out)
    half* wb0 = h2b + LROWS * H2LD2; // 9216
    half* wb1 = wb0 + WBH;           // 9216
    __shared__ float W1t[CIN * C1];
    __shared__ float s_nbr[LPTS][KNN][3];
    __shared__ float s_dist[LPTS][KNN];
    __shared__ float s_xn[LPTS][3];

    const int tid = threadIdx.x, warp = tid >> 5;
    const size_t pt0 = (size_t)blockIdx.x * LPTS;

    for (int i = tid; i < CIN * C1; i += 256) { int o = i / CIN, c = i % CIN; W1t[c * C1 + o] = w1[i]; }
    {   // W2 -> wb0 (512 uint4)
        const uint4* s = (const uint4*)g_w2h;
#pragma unroll
        for (int i = tid; i < 512; i += 256) { int o = i >> 3, q = i & 7; *(uint4*)(wb0 + o * H2LD2 + q * 8) = s[i]; }
    }

    if (tid < LPTS * KNN) {
        int p = tid / KNN, k = tid % KNN;
        size_t pt = pt0 + p;
        int b = (int)(pt >> 12), n = (int)(pt & (NPTS - 1));
        const float* xb = x + (size_t)b * 3 * NPTS;
        int nb = g_idx[pt * KNN + k];
        float c0 = xb[n], c1 = xb[NPTS + n], c2 = xb[2 * NPTS + n];
        float n0 = xb[nb], n1 = xb[NPTS + nb], n2 = xb[2 * NPTS + nb];
        s_nbr[p][k][0] = n0; s_nbr[p][k][1] = n1; s_nbr[p][k][2] = n2;
        float d0 = n0 - c0, d1 = n1 - c1, d2 = n2 - c2;
        s_dist[p][k] = sqrtf(fmaf(d0, d0, fmaf(d1, d1, d2 * d2)) + 1e-12f);
        if (k < 3) s_xn[p][k] = xb[k * NPTS + n];
    }
    __syncthreads();

    // ---- L1 scalar -> hb, x1 -> cat[0:64] ----
    {
        int o = tid & 63;
#pragma unroll
        for (int pi = 0; pi < 2; ++pi) {
            int p = (tid >> 6) + pi * 4;
            float base = 0.f;
#pragma unroll
            for (int d = 0; d < 3; ++d) base = fmaf(W1t[d * C1 + o], s_xn[p][d], base);
#pragma unroll
            for (int j = 0; j < KNN; ++j) base = fmaf(W1t[(6 + j) * C1 + o], s_dist[p][j], base);
            float wa = W1t[3 * C1 + o], wb = W1t[4 * C1 + o], wc = W1t[5 * C1 + o];
            float mx = 0.f;
#pragma unroll
            for (int k = 0; k < KNN; ++k) {
                float v = fmaf(wa, s_nbr[p][k][0], fmaf(wb, s_nbr[p][k][1], fmaf(wc, s_nbr[p][k][2], base)));
                v = fmaxf(v, 0.f);
                mx = fmaxf(mx, v);
                hb[(p * KNN + k) * HBLD + o] = __float2half_rn(v);
            }
            g_cat[(pt0 + p) * CCAT + o] = __float2half_rn(mx);
        }
    }
    __syncthreads();

    // ---- Phase: L2 MMA (wb0), prefetch W3 -> wb1 ----
    {
        uint4 pw[4];
        const uint4* s3 = (const uint4*)g_w3h;
#pragma unroll
        for (int i = 0; i < 4; ++i) pw[i] = s3[tid + i * 256];

        const int nt = warp & 3, hf = warp >> 2;
        HA fa; HB fb; HCf fc[5];
#pragma unroll
        for (int i = 0; i < 5; ++i) wmma::fill_fragment(fc[i], 0.f);
#pragma unroll
        for (int kt = 0; kt < 4; ++kt) {
            wmma::load_matrix_sync(fb, wb0 + nt * 16 * H2LD2 + kt * 16, H2LD2);
#pragma unroll
            for (int i = 0; i < 5; ++i) {
                wmma::load_matrix_sync(fa, hb + (hf * 5 + i) * 16 * HBLD + kt * 16, HBLD);
                wmma::mma_sync(fc[i], fa, fb, fc[i]);
            }
        }
#pragma unroll
        for (int i = 0; i < 5; ++i)
            store_relu_half(h2b + (hf * 5 + i) * 16 * H2LD2 + nt * 16, H2LD2, fc[i]);

#pragma unroll
        for (int i = 0; i < 4; ++i) {
            int lin = tid + i * 256, o = lin >> 3, q = lin & 7;
            *(uint4*)(wb1 + o * H2LD2 + q * 8) = pw[i];
        }
    }
    __syncthreads();

    // ---- Phase: x2 epi (h2b, hmax2) + L3 MMA (h2b -> hb, wb1), prefetch W4c0 -> wb0 ----
    {
        uint4 pw[4];
        const uint4* s4 = (const uint4*)g_w4h;
#pragma unroll
        for (int i = 0; i < 4; ++i) pw[i] = s4[tid + i * 256];

        {   // x2: 8 pts x 32 half2 cols
            int p = tid >> 5, c = tid & 31;
            half2 mx = __floats2half2_rn(0.f, 0.f);
#pragma unroll
            for (int k = 0; k < KNN; ++k)
                mx = __hmax2(mx, *(half2*)(h2b + (p * KNN + k) * H2LD2 + 2 * c));
            *(half2*)(&g_cat[(pt0 + p) * CCAT + 64 + 2 * c]) = mx;
        }

        HA fa; HB fb;
#pragma unroll
        for (int pass = 0; pass < 2; ++pass) {
            HCf fc[5];
#pragma unroll
            for (int i = 0; i < 5; ++i) wmma::fill_fragment(fc[i], 0.f);
#pragma unroll
            for (int kt = 0; kt < 4; ++kt) {
                wmma::load_matrix_sync(fb, wb1 + warp * 16 * H2LD2 + kt * 16, H2LD2);
#pragma unroll
                for (int i = 0; i < 5; ++i) {
                    wmma::load_matrix_sync(fa, h2b + (pass * 5 + i) * 16 * H2LD2 + kt * 16, H2LD2);
                    wmma::mma_sync(fc[i], fa, fb, fc[i]);
                }
            }
#pragma unroll
            for (int i = 0; i < 5; ++i)
                store_relu_half(hb + (pass * 5 + i) * 16 * HBLD + warp * 16, HBLD, fc[i]);
        }

#pragma unroll
        for (int i = 0; i < 4; ++i) {
            int lin = tid + i * 256, o = lin >> 4, q = lin & 15;
            *(uint4*)(wb0 + o * HBLD + q * 8) = pw[i];
        }
    }
    __syncthreads();

    // ---- Phase: x3 epi (hb, hmax2) + L4c0 MMA (hb -> h2b, wb0), prefetch c1 -> wb1 ----
    // ---- then per-chunk: sync, x4 epi, sync, next chunk MMA ----
    for (int co = 0; co < 4; ++co) {
        half* cur = (co & 1) ? wb1 : wb0;
        half* nxt = (co & 1) ? wb0 : wb1;
        uint4 pw[4];
        if (co < 3) {
            const uint4* s4 = (const uint4*)(g_w4h + (size_t)(co + 1) * 64 * 128);
#pragma unroll
            for (int i = 0; i < 4; ++i) pw[i] = s4[tid + i * 256];
        }
        if (co == 0) {   // x3 epi merged here: 8 pts x 64 half2 cols = 512 slots
#pragma unroll
            for (int pi = 0; pi < 2; ++pi) {
                int slot = tid + pi * 256;
                int p = slot >> 6, c = slot & 63;
                half2 mx = __floats2half2_rn(0.f, 0.f);
#pragma unroll
                for (int k = 0; k < KNN; ++k)
                    mx = __hmax2(mx, *(half2*)(hb + (p * KNN + k) * HBLD + 2 * c));
                *(half2*)(&g_cat[(pt0 + p) * CCAT + 128 + 2 * c]) = mx;
            }
        }
        {
            const int nt = warp & 3, hf = warp >> 2;
            HA fa; HB fb; HCf fc[5];
#pragma unroll
            for (int i = 0; i < 5; ++i) wmma::fill_fragment(fc[i], 0.f);
#pragma unroll
            for (int kt = 0; kt < 8; ++kt) {
                wmma::load_matrix_sync(fb, cur + nt * 16 * HBLD + kt * 16, HBLD);
#pragma unroll
                for (int i = 0; i < 5; ++i) {
                    wmma::load_matrix_sync(fa, hb + (hf * 5 + i) * 16 * HBLD + kt * 16, HBLD);
                    wmma::mma_sync(fc[i], fa, fb, fc[i]);
                }
            }
#pragma unroll
            for (int i = 0; i < 5; ++i)
                store_relu_half(h2b + (hf * 5 + i) * 16 * H2LD2 + nt * 16, H2LD2, fc[i]);
        }
        if (co < 3) {
#pragma unroll
            for (int i = 0; i < 4; ++i) {
                int lin = tid + i * 256, o = lin >> 4, q = lin & 15;
                *(uint4*)(nxt + o * HBLD + q * 8) = pw[i];
            }
        }
        __syncthreads();
        {   // x4 epi: 8 pts x 32 half2 cols
            int p = tid >> 5, c = tid & 31;
            half2 mx = __floats2half2_rn(0.f, 0.f);
#pragma unroll
            for (int k = 0; k < KNN; ++k)
                mx = __hmax2(mx, *(half2*)(h2b + (p * KNN + k) * H2LD2 + 2 * c));
            *(half2*)(&g_cat[(pt0 + p) * CCAT + 256 + co * 64 + 2 * c]) = mx;
        }
        if (co < 3) __syncthreads();
    }
}

// ===================== Kernel 3: L5 tiled GEMM (wmma fp16) =====================
#define KC5   64
#define ALD5  72
#define TILEH (128 * ALD5)

__global__ __launch_bounds__(256, 2) void l5_kernel(float* __restrict__ out) {
    extern __shared__ half hsm[];
    half* bufA[2] = { hsm,         hsm + 2 * TILEH };
    half* bufB[2] = { hsm + TILEH, hsm + 3 * TILEH };

    const int tid = threadIdx.x, warp = tid >> 5;
    const int n0 = blockIdx.x * 128;
    const int o0 = blockIdx.y * 128;
    const int b  = blockIdx.z;
    const half* catg = g_cat + ((size_t)b * NPTS + n0) * CCAT;
    const half* wg   = g_w5h + (size_t)o0 * CCAT;
    const int wr = warp >> 2, wc = warp & 3;

    HCf fc[4][2];
#pragma unroll
    for (int i = 0; i < 4; ++i) { wmma::fill_fragment(fc[i][0], 0.f); wmma::fill_fragment(fc[i][1], 0.f); }

    auto stage = [&](int kc, int bi) {
        half* pa = bufA[bi]; half* pb = bufB[bi];
#pragma unroll
        for (int it = 0; it < 4; ++it) {
            int lin = tid + it * 256;
            int r = lin >> 3, q = lin & 7;
            *(uint4*)(pa + r * ALD5 + q * 8) = *(const uint4*)(wg   + (size_t)r * CCAT + kc * KC5 + q * 8);
            *(uint4*)(pb + r * ALD5 + q * 8) = *(const uint4*)(catg + (size_t)r * CCAT + kc * KC5 + q * 8);
        }
    };

    stage(0, 0);
    __syncthreads();

    HA fa; HB fb;
    for (int kc = 0; kc < 8; ++kc) {
        const int cur = kc & 1;
        if (kc + 1 < 8) stage(kc + 1, cur ^ 1);
        const half* A = bufA[cur];
        const half* B = bufB[cur];
#pragma unroll
        for (int kt = 0; kt < 4; ++kt) {
#pragma unroll
            for (int j = 0; j < 2; ++j) {
                wmma::load_matrix_sync(fb, B + (wc * 32 + j * 16) * ALD5 + kt * 16, ALD5);
#pragma unroll
                for (int i = 0; i < 4; ++i) {
                    wmma::load_matrix_sync(fa, A + (wr * 64 + i * 16) * ALD5 + kt * 16, ALD5);
                    wmma::mma_sync(fc[i][j], fa, fb, fc[i][j]);
                }
            }
        }
        __syncthreads();
    }

    float* scratch = (float*)hsm;
#pragma unroll
    for (int i = 0; i < 4; ++i)
#pragma unroll
        for (int j = 0; j < 2; ++j)
            wmma::store_matrix_sync(scratch + (wr * 64 + i * 16) * 132 + wc * 32 + j * 16,
                                    fc[i][j], 132, wmma::mem_row_major);
    __syncthreads();

    for (int i = tid; i < 128 * 128; i += 256) {
        int o = i >> 7, n = i & 127;
        out[((size_t)b * EMB + o0 + o) * NPTS + n0 + n] = fmaxf(scratch[o * 132 + n], 0.f);
    }
}

// ===================== launch =====================
extern "C" void kernel_launch(void* const* d_in, const int* in_sizes, int n_in,
                              void* d_out, int out_size) {
    const float* x  = (const float*)d_in[0];
    const float* w1 = (const float*)d_in[1];
    const float* w2 = (const float*)d_in[2];
    const float* w3 = (const float*)d_in[3];
    const float* w4 = (const float*)d_in[4];
    const float* w5 = (const float*)d_in[5];
    float* out = (float*)d_out;

    const int knn_smem   = NPTS * sizeof(float4);                                        // 64 KB
    const int l1234_smem = (LROWS * HBLD + LROWS * H2LD2 + 2 * WBH) * sizeof(half);      // ~101 KB
    const int l5_smem    = 4 * TILEH * sizeof(half);                                     // 72 KB
    cudaFuncSetAttribute(knn_kernel,   cudaFuncAttributeMaxDynamicSharedMemorySize, knn_smem);
    cudaFuncSetAttribute(l1234_kernel, cudaFuncAttributeMaxDynamicSharedMemorySize, l1234_smem);
    cudaFuncSetAttribute(l5_kernel,    cudaFuncAttributeMaxDynamicSharedMemorySize, l5_smem);

    wconv_all<<<(W2N + W3N + W4N + W5N) / 1024, 256>>>(w2, w3, w4, w5);
    knn_kernel<<<dim3(NPTS / 16, BATCH), 512, knn_smem>>>(x);
    l1234_kernel<<<(BATCH * NPTS) / LPTS, 256, l1234_smem>>>(x, w1);
    l5_kernel<<<dim3(NPTS / 128, EMB / 128, BATCH), 256, l5_smem>>>(out);
}